// round 10
// baseline (speedup 1.0000x reference)
#include <cuda_runtime.h>
#include <math.h>
#include <stdint.h>
#include <float.h>

#define MAXB    128
#define CAP     4096
#define NBINS   2048     // coarse subsample bins
#define FB      4096     // fine ranking bins
#define S_SPLIT 4
#define NTA     1024
#define NTB     256
#define NTC     1024

// Global staging
__device__ float g_thr [MAXB];
__device__ float g_pmax[MAXB * S_SPLIT];
__device__ float g_psum[MAXB * S_SPLIT];
__device__ int   g_cnt [MAXB];
__device__ float g_cval[MAXB * CAP];
__device__ int   g_cidx[MAXB * CAP];

__device__ __forceinline__ int bin_of(float x) {
    int b = (int)floorf((x + 32.0f) * 32.0f);   // width 1/32 over [-32, 32]
    b = b < 0 ? 0 : b;
    return b > (NBINS - 1) ? (NBINS - 1) : b;
}

__device__ __forceinline__ float warp_red_sum(float v) {
    #pragma unroll
    for (int o = 16; o; o >>= 1) v += __shfl_xor_sync(0xffffffffu, v, o);
    return v;
}
__device__ __forceinline__ float warp_red_max(float v) {
    #pragma unroll
    for (int o = 16; o; o >>= 1) v = fmaxf(v, __shfl_xor_sync(0xffffffffu, v, o));
    return v;
}

// 1024-thread block scans
__device__ __forceinline__ float block_incl_scan(float v, float* wsum, int lane, int wid) {
    #pragma unroll
    for (int off = 1; off < 32; off <<= 1) {
        float n = __shfl_up_sync(0xffffffffu, v, off);
        if (lane >= off) v += n;
    }
    __syncthreads();
    if (lane == 31) wsum[wid] = v;
    __syncthreads();
    if (wid == 0) {
        float w = wsum[lane];
        #pragma unroll
        for (int off = 1; off < 32; off <<= 1) {
            float n = __shfl_up_sync(0xffffffffu, w, off);
            if (lane >= off) w += n;
        }
        wsum[lane] = w;
    }
    __syncthreads();
    return v + (wid ? wsum[wid - 1] : 0.f);
}
__device__ __forceinline__ int block_incl_scan_int(int v, int* wsum, int lane, int wid) {
    #pragma unroll
    for (int off = 1; off < 32; off <<= 1) {
        int n = __shfl_up_sync(0xffffffffu, v, off);
        if (lane >= off) v += n;
    }
    __syncthreads();
    if (lane == 31) wsum[wid] = v;
    __syncthreads();
    if (wid == 0) {
        int w = wsum[lane];
        #pragma unroll
        for (int off = 1; off < 32; off <<= 1) {
            int n = __shfl_up_sync(0xffffffffu, w, off);
            if (lane >= off) w += n;
        }
        wsum[lane] = w;
    }
    __syncthreads();
    return v + (wid ? wsum[wid - 1] : 0);
}

// order-preserving float <-> u32
__device__ __forceinline__ unsigned fmap(float x) {
    unsigned fb = __float_as_uint(x);
    return (fb & 0x80000000u) ? ~fb : (fb | 0x80000000u);
}
__device__ __forceinline__ float funmap(unsigned mu) {
    unsigned fb = (mu & 0x80000000u) ? (mu & 0x7FFFFFFFu) : ~mu;
    return __uint_as_float(fb);
}
__device__ __forceinline__ bool kv_gt(unsigned k1, unsigned p1, unsigned k2, unsigned p2) {
    return (k1 > k2) || (k1 == k2 && p1 < p2);   // key desc, idx asc
}
__device__ __forceinline__ void ce_sh(unsigned* kv, unsigned* pv, int i, int j, int K) {
    unsigned k1 = kv[i], p1 = pv[i], k2 = kv[i + j], p2 = pv[i + j];
    bool sw = ((i & K) == 0) ? kv_gt(k2, p2, k1, p1) : kv_gt(k1, p1, k2, p2);
    if (sw) { kv[i] = k2; pv[i] = p2; kv[i + j] = k1; pv[i + j] = p1; }
}

// =============== kA: subsample threshold per row (128 x 1024) ===============
__global__ void __launch_bounds__(NTA) kA(const float* __restrict__ logits, int V)
{
    const int row = blockIdx.x;
    const int tid = threadIdx.x;
    const int lane = tid & 31, wid = tid >> 5;
    __shared__ int hist[NBINS];
    __shared__ int iwsum[32];
    __shared__ int s_bt;

    if (tid == 0) { g_cnt[row] = 0; s_bt = 1024; }
    if (V <= CAP) {
        if (tid == 0) g_thr[row] = -FLT_MAX;
        return;
    }
    const float* lrow = logits + (size_t)row * V;
    const int V4 = V >> 2;
    const float4* l4 = (const float4*)lrow;
    const int need = V < 1024 ? V : 1024;

    for (int t = tid; t < NBINS; t += NTA) hist[t] = 0;
    __syncthreads();

    // 4 contiguous 1024-float4 chunks (coalesced, 64KB of the row)
    int Vq = V4 >> 2; if (Vq < 1) Vq = 1;
    for (int k = tid; k < 4096; k += NTA) {
        int c = k >> 10;
        int t = k & 1023;
        int pos = c * Vq + (t % Vq);
        if (pos >= V4) pos = V4 - 1;
        float4 v = l4[pos];
        if (v.x > 2.0f) atomicAdd(&hist[bin_of(v.x)], 1);
        if (v.y > 2.0f) atomicAdd(&hist[bin_of(v.y)], 1);
        if (v.z > 2.0f) atomicAdd(&hist[bin_of(v.z)], 1);
        if (v.w > 2.0f) atomicAdd(&hist[bin_of(v.w)], 1);
    }
    __syncthreads();
    // target expected true count ~1.55*need
    const int subN = 16384;
    int tgt = (int)(((long long)need * 31LL * subN) / (20LL * (long long)V));
    if (tgt < 1) tgt = 1;
    int b = 2047 - tid;
    int v = (tid < 960) ? hist[b] : 0;
    int sfx = block_incl_scan_int(v, iwsum, lane, wid);
    if (tid < 960 && sfx >= tgt && sfx - v < tgt) s_bt = b;
    __syncthreads();
    if (tid == 0) g_thr[row] = (float)s_bt * 0.03125f - 32.0f;
}

// =============== kB: zero + scan + gather per row-slice (128*S x 256) ========
__global__ void __launch_bounds__(NTB) kB(const float* __restrict__ logits,
                                          const float* __restrict__ temps,
                                          float* __restrict__ out,
                                          int V, int B, int tokens_first)
{
    const int row = blockIdx.x >> 2;          // S_SPLIT == 4
    const int sp  = blockIdx.x & 3;
    const int tid = threadIdx.x;
    const int lane = tid & 31, wid = tid >> 5;
    __shared__ float wred[8];

    const int Vs = (((V + S_SPLIT - 1) / S_SPLIT) + 3) & ~3;
    const int st = sp * Vs;
    const int en = (st + Vs < V) ? (st + Vs) : V;

    float* probs_out = tokens_first ? (out + B) : out;
    float* prow = probs_out + (size_t)row * V;
    const float* lrow = logits + (size_t)row * V;
    const float invT = 1.0f / temps[row];
    const float xthr = g_thr[row];

    float s0 = 0.f, s1 = 0.f, s2 = 0.f, s3 = 0.f, mx = -FLT_MAX;

    if (st < V) {
        const int q0 = st >> 2;
        const int q1 = en >> 2;                 // st 4-aligned; en maybe not (last slice)
        const float4* l4 = (const float4*)lrow;
        float4* p4 = (float4*)prow;
        const float4 z4 = make_float4(0.f, 0.f, 0.f, 0.f);

        // zero output slice (streaming, drains under the scan)
        for (int q = q0 + tid; q < q1; q += NTB) __stcs(p4 + q, z4);
        for (int t = (q1 << 2) + tid; t < en; t += NTB) __stcs(prow + t, 0.f);

        #define GATHER4(vv, qq)                                                            \
            { _Pragma("unroll")                                                            \
              for (int c = 0; c < 4; c++) {                                                \
                float x = (c==0)?(vv).x:(c==1)?(vv).y:(c==2)?(vv).z:(vv).w;                \
                if (x >= xthr) {                                                           \
                    int pos = atomicAdd(&g_cnt[row], 1);                                   \
                    if (pos < CAP) { g_cval[row*CAP+pos] = x;                              \
                                     g_cidx[row*CAP+pos] = ((qq) << 2) + c; }              \
                } } }

        int q = q0 + tid;
        for (; q + 3 * NTB < q1; q += 4 * NTB) {
            float4 va = l4[q];
            float4 vb = l4[q + NTB];
            float4 vc = l4[q + 2 * NTB];
            float4 vd = l4[q + 3 * NTB];
            mx = fmaxf(mx, fmaxf(fmaxf(va.x, va.y), fmaxf(va.z, va.w)));
            mx = fmaxf(mx, fmaxf(fmaxf(vb.x, vb.y), fmaxf(vb.z, vb.w)));
            mx = fmaxf(mx, fmaxf(fmaxf(vc.x, vc.y), fmaxf(vc.z, vc.w)));
            mx = fmaxf(mx, fmaxf(fmaxf(vd.x, vd.y), fmaxf(vd.z, vd.w)));
            s0 += __expf(va.x * invT) + __expf(va.y * invT) + __expf(va.z * invT) + __expf(va.w * invT);
            s1 += __expf(vb.x * invT) + __expf(vb.y * invT) + __expf(vb.z * invT) + __expf(vb.w * invT);
            s2 += __expf(vc.x * invT) + __expf(vc.y * invT) + __expf(vc.z * invT) + __expf(vc.w * invT);
            s3 += __expf(vd.x * invT) + __expf(vd.y * invT) + __expf(vd.z * invT) + __expf(vd.w * invT);
            GATHER4(va, q);
            GATHER4(vb, q + NTB);
            GATHER4(vc, q + 2 * NTB);
            GATHER4(vd, q + 3 * NTB);
        }
        for (; q < q1; q += NTB) {
            float4 v = l4[q];
            mx = fmaxf(mx, fmaxf(fmaxf(v.x, v.y), fmaxf(v.z, v.w)));
            s0 += __expf(v.x * invT) + __expf(v.y * invT) + __expf(v.z * invT) + __expf(v.w * invT);
            GATHER4(v, q);
        }
        #undef GATHER4
        for (int t = (q1 << 2) + tid; t < en; t += NTB) {
            float x = lrow[t];
            mx = fmaxf(mx, x);
            s0 += __expf(x * invT);
            if (x >= xthr) {
                int pos = atomicAdd(&g_cnt[row], 1);
                if (pos < CAP) { g_cval[row * CAP + pos] = x; g_cidx[row * CAP + pos] = t; }
            }
        }
    }
    float s = (s0 + s1) + (s2 + s3);
    s = warp_red_sum(s);
    if (lane == 0) wred[wid] = s;
    __syncthreads();
    if (wid == 0 && lane < 8) {
        float t = wred[lane];
        #pragma unroll
        for (int o = 4; o; o >>= 1) t += __shfl_xor_sync(0xffu, t, o);
        if (lane == 0) g_psum[row * S_SPLIT + sp] = t;
    }
    __syncthreads();
    mx = warp_red_max(mx);
    if (lane == 0) wred[wid] = mx;
    __syncthreads();
    if (wid == 0 && lane < 8) {
        float t = wred[lane];
        #pragma unroll
        for (int o = 4; o; o >>= 1) t = fmaxf(t, __shfl_xor_sync(0xffu, t, o));
        if (lane == 0) g_pmax[row * S_SPLIT + sp] = t;
    }
}

// =============== kC: combine + rank + masks + sample + scatter (128 x 1024) ==
__global__ void __launch_bounds__(NTC) kC(const float* __restrict__ logits,
                                          const float* __restrict__ temps,
                                          const int*   __restrict__ top_ks,
                                          const float* __restrict__ top_ps,
                                          const float* __restrict__ min_ps,
                                          const float* __restrict__ u,
                                          float* __restrict__ out,
                                          int V, int B, int tokens_first)
{
    const int row = blockIdx.x;
    const int tid = threadIdx.x;
    const int lane = tid & 31, wid = tid >> 5;

    __shared__ unsigned arena[8192];      // 32 KB phase-aliased
    __shared__ float wred[32];
    __shared__ int   iwsum[32];
    __shared__ float s_S, s_lo;
    __shared__ int   s_cnt, s_bad;
    __shared__ float sh_p0, sh_tot;

    const float* lrow = logits + (size_t)row * V;
    const float invT = 1.0f / temps[row];
    const int need = V < 1024 ? V : 1024;
    float* probs_out = tokens_first ? (out + B) : out;
    float* prow = probs_out + (size_t)row * V;

    // ---- combine partials deterministically ----
    float S = 0.f, mxv = -FLT_MAX;
    #pragma unroll
    for (int s = 0; s < S_SPLIT; s++) {
        S += g_psum[row * S_SPLIT + s];
        mxv = fmaxf(mxv, g_pmax[row * S_SPLIT + s]);
    }
    float shift = 0.f;
    float mxT = mxv * invT;
    if (mxT > 80.f || !isfinite(S)) shift = mxT;
    if (shift != 0.f) {                   // rare overflow-safe recompute (precise)
        float sacc = 0.f;
        for (int t = tid; t < V; t += NTC) sacc = sacc + expf(lrow[t] * invT - shift);
        sacc = warp_red_sum(sacc);
        if (lane == 0) wred[wid] = sacc;
        __syncthreads();
        if (wid == 0) { float t = warp_red_sum(wred[lane]); if (lane == 0) s_S = t; }
        __syncthreads();
        S = s_S;
    }

    int C = g_cnt[row];
    if (tid == 0) { s_bad = 0; s_lo = g_thr[row]; }
    __syncthreads();

    if (!(C >= need && C <= CAP)) {
        // ---- FALLBACK (~never): exact coarse hist -> threshold -> re-gather ----
        int* hist = (int*)arena;
        for (int t = tid; t < NBINS; t += NTC) hist[t] = 0;
        __syncthreads();
        for (int t = tid; t < V; t += NTC) atomicAdd(&hist[bin_of(lrow[t])], 1);
        __syncthreads();
        if (tid == 0) {
            int acc = 0, bt2 = 0;
            for (int b = NBINS - 1; b >= 0; b--) {
                int na = acc + hist[b];
                if (na >= need) { bt2 = (na <= CAP) ? b : (b + 1); break; }
                acc = na;
            }
            s_cnt = 0;
            s_lo = (float)bt2 * 0.03125f - 32.0f - 0.0625f;
            iwsum[0] = bt2;
        }
        __syncthreads();
        const int bt2 = iwsum[0];
        for (int t = tid; t < V; t += NTC) {
            float x = lrow[t];
            if (bin_of(x) >= bt2) {
                int pos = atomicAdd(&s_cnt, 1);
                if (pos < CAP) { g_cval[row * CAP + pos] = x; g_cidx[row * CAP + pos] = t; }
            }
        }
        __syncthreads();
        C = s_cnt;
    }
    C = C < CAP ? C : CAP;
    __syncthreads();

    // ---- ranking ----
    const float lo = s_lo, hi = mxv;
    const float range = hi - lo;
    int*      bins = (int*)arena;
    unsigned* skv  = arena + 4096;
    unsigned* skp  = arena + 6144;
    unsigned *pk = skv, *pp = skp;
    bool fast = (C <= 2048) && (range > 0.f) && isfinite(range);

    if (fast) {
        const float scale = (float)FB / range;
        unsigned k0 = 0, k1 = 0; int i0 = 0, i1 = 0, b0 = 0, b1 = 0;
        float x0 = 0.f, x1 = 0.f;
        if (tid < C)        { x0 = g_cval[row * CAP + tid];        i0 = g_cidx[row * CAP + tid];        k0 = fmap(x0); }
        if (tid + 1024 < C) { x1 = g_cval[row * CAP + tid + 1024]; i1 = g_cidx[row * CAP + tid + 1024]; k1 = fmap(x1); }
        #pragma unroll
        for (int t = 0; t < 4; t++) bins[tid + t * NTC] = 0;
        __syncthreads();
        if (tid < C) {
            b0 = (int)((x0 - lo) * scale); b0 = b0 < 0 ? 0 : (b0 > FB - 1 ? FB - 1 : b0);
            atomicAdd(&bins[b0], 1);
        }
        if (tid + 1024 < C) {
            b1 = (int)((x1 - lo) * scale); b1 = b1 < 0 ? 0 : (b1 > FB - 1 ? FB - 1 : b1);
            atomicAdd(&bins[b1], 1);
        }
        __syncthreads();
        int c0c = bins[4095 - 4 * tid];
        int c1c = bins[4094 - 4 * tid];
        int c2c = bins[4093 - 4 * tid];
        int c3c = bins[4092 - 4 * tid];
        int tot4 = c0c + c1c + c2c + c3c;
        int base = block_incl_scan_int(tot4, iwsum, lane, wid) - tot4;
        bins[4095 - 4 * tid] = base;
        bins[4094 - 4 * tid] = base + c0c;
        bins[4093 - 4 * tid] = base + c0c + c1c;
        bins[4092 - 4 * tid] = base + c0c + c1c + c2c;
        __syncthreads();
        if (tid < C)        { int sl = atomicAdd(&bins[b0], 1); skv[sl] = k0; skp[sl] = (unsigned)i0; }
        if (tid + 1024 < C) { int sl = atomicAdd(&bins[b1], 1); skv[sl] = k1; skp[sl] = (unsigned)i1; }
        __syncthreads();
        #pragma unroll
        for (int e = 0; e < 2; e++) {
            int ii = tid + e * 1024;
            if (ii < C) {
                int bi = (int)((funmap(skv[ii]) - lo) * scale); bi = bi < 0 ? 0 : (bi > FB - 1 ? FB - 1 : bi);
                int bp = -1;
                if (ii > 0) {
                    bp = (int)((funmap(skv[ii - 1]) - lo) * scale); bp = bp < 0 ? 0 : (bp > FB - 1 ? FB - 1 : bp);
                }
                if (bi != bp) {
                    int L = 1;
                    while (ii + L < C && L <= 16) {
                        int bn = (int)((funmap(skv[ii + L]) - lo) * scale); bn = bn < 0 ? 0 : (bn > FB - 1 ? FB - 1 : bn);
                        if (bn != bi) break;
                        L++;
                    }
                    if (L > 16) { atomicExch(&s_bad, 1); }
                    else if (L > 1) {
                        unsigned lk[16], lp[16];
                        for (int t = 0; t < L; t++) { lk[t] = skv[ii + t]; lp[t] = skp[ii + t]; }
                        for (int a = 1; a < L; a++) {
                            unsigned ck = lk[a], cp = lp[a];
                            int b2 = a - 1;
                            while (b2 >= 0 && !kv_gt(lk[b2], lp[b2], ck, cp)) {
                                lk[b2 + 1] = lk[b2]; lp[b2 + 1] = lp[b2]; b2--;
                            }
                            lk[b2 + 1] = ck; lp[b2 + 1] = cp;
                        }
                        for (int t = 0; t < L; t++) { skv[ii + t] = lk[t]; skp[ii + t] = lp[t]; }
                    }
                }
            }
        }
        __syncthreads();
        if (s_bad) fast = false;
        __syncthreads();
    }

    if (!fast) {
        unsigned* fkv = arena;
        unsigned* fkp = arena + 4096;
        for (int ii = tid; ii < CAP; ii += NTC) {
            unsigned key = 0u, pay = 0xFFFFFFFFu;
            if (ii < C) { key = fmap(g_cval[row * CAP + ii]); pay = (unsigned)g_cidx[row * CAP + ii]; }
            fkv[ii] = key; fkp[ii] = pay;
        }
        __syncthreads();
        for (int K = 2; K <= CAP; K <<= 1) {
            int j = K >> 1;
            for (; j >= 64; j >>= 1) {
                for (int c = tid; c < (CAP >> 1); c += NTC) {
                    int ii = ((c & ~(j - 1)) << 1) | (c & (j - 1));
                    ce_sh(fkv, fkp, ii, j, K);
                }
                __syncthreads();
            }
            for (; j >= 1; j >>= 1) {
                for (int c = tid; c < (CAP >> 1); c += NTC) {
                    int ii = ((c & ~(j - 1)) << 1) | (c & (j - 1));
                    ce_sh(fkv, fkp, ii, j, K);
                }
                __syncwarp();
            }
            __syncthreads();
        }
        pk = fkv; pp = fkp;
    }

    // ---- masks (reference order) + inverse-CDF sample + scatter ----
    float p = 0.f;
    int   myidx = 0;
    if (tid < C) {
        p = expf(funmap(pk[tid]) * invT - shift) / S;
        myidx = (int)pp[tid];
    }
    if (tid == 0) sh_p0 = p;

    float cumincl = block_incl_scan(p, wred, lane, wid);   // pre-mask cumsum

    const int   tk  = top_ks[row];
    const float tp  = top_ps[row];
    const float thr = sh_p0 * min_ps[row];
    float q = p;
    if (tid >= tk)        q = 0.f;   // top-k
    if (cumincl - q > tp) q = 0.f;   // top-p (cumsum computed pre-mask)
    if (q < thr)          q = 0.f;   // min-p

    float cq = block_incl_scan(q, wred, lane, wid);
    if (tid == NTC - 1) sh_tot = cq;
    __syncthreads();
    const float tot  = sh_tot;
    const float uval = u[row];

    int rank = __syncthreads_count((cq / tot < uval) ? 1 : 0);
    if (rank > NTC - 1) rank = NTC - 1;
    if (rank > V - 1) rank = V - 1;

    if (tid == 0 && tokens_first) {
        out[row] = (float)(int)pp[rank];
    }
    if (q > 0.f) {
        prow[myidx] = q / tot;       // row zeroed by kB (prior kernel)
    }
}

extern "C" void kernel_launch(void* const* d_in, const int* in_sizes, int n_in,
                              void* d_out, int out_size)
{
    const float* logits = (const float*)d_in[0];
    const float* temps  = (const float*)d_in[1];
    const int*   topks  = (const int*)  d_in[2];
    const float* topps  = (const float*)d_in[3];
    const float* minps  = (const float*)d_in[4];
    const float* u      = (const float*)d_in[5];

    const int B = in_sizes[1];
    const int V = in_sizes[0] / B;
    float* out = (float*)d_out;
    int tokens_first = (out_size == B + B * V) ? 1 : 0;

    kA<<<B, NTA>>>(logits, V);
    kB<<<B * S_SPLIT, NTB>>>(logits, temps, out, V, B, tokens_first);
    kC<<<B, NTC>>>(logits, temps, topks, topps, minps, u, out, V, B, tokens_first);
}

// round 11
// speedup vs baseline: 1.8830x; 1.8830x over previous
#include <cuda_runtime.h>
#include <math.h>
#include <stdint.h>
#include <float.h>

#define MAXB  128
#define CAP   4096
#define NBINS 2048     // coarse subsample bins
#define FB    4096     // fine ranking bins
#define NT    1024

// Global candidate staging (written phase 2/3, read phase 4)
__device__ float g_cval[MAXB * CAP];
__device__ int   g_cidx[MAXB * CAP];

__device__ __forceinline__ int bin_of(float x) {
    int b = (int)floorf((x + 32.0f) * 32.0f);   // width 1/32 over [-32, 32]
    b = b < 0 ? 0 : b;
    return b > (NBINS - 1) ? (NBINS - 1) : b;
}

__device__ __forceinline__ float warp_red_sum(float v) {
    #pragma unroll
    for (int o = 16; o; o >>= 1) v += __shfl_xor_sync(0xffffffffu, v, o);
    return v;
}
__device__ __forceinline__ float warp_red_max(float v) {
    #pragma unroll
    for (int o = 16; o; o >>= 1) v = fmaxf(v, __shfl_xor_sync(0xffffffffu, v, o));
    return v;
}

__device__ __forceinline__ float block_incl_scan(float v, float* wsum, int lane, int wid) {
    #pragma unroll
    for (int off = 1; off < 32; off <<= 1) {
        float n = __shfl_up_sync(0xffffffffu, v, off);
        if (lane >= off) v += n;
    }
    __syncthreads();
    if (lane == 31) wsum[wid] = v;
    __syncthreads();
    if (wid == 0) {
        float w = wsum[lane];
        #pragma unroll
        for (int off = 1; off < 32; off <<= 1) {
            float n = __shfl_up_sync(0xffffffffu, w, off);
            if (lane >= off) w += n;
        }
        wsum[lane] = w;
    }
    __syncthreads();
    return v + (wid ? wsum[wid - 1] : 0.f);
}

__device__ __forceinline__ int block_incl_scan_int(int v, int* wsum, int lane, int wid) {
    #pragma unroll
    for (int off = 1; off < 32; off <<= 1) {
        int n = __shfl_up_sync(0xffffffffu, v, off);
        if (lane >= off) v += n;
    }
    __syncthreads();
    if (lane == 31) wsum[wid] = v;
    __syncthreads();
    if (wid == 0) {
        int w = wsum[lane];
        #pragma unroll
        for (int off = 1; off < 32; off <<= 1) {
            int n = __shfl_up_sync(0xffffffffu, w, off);
            if (lane >= off) w += n;
        }
        wsum[lane] = w;
    }
    __syncthreads();
    return v + (wid ? wsum[wid - 1] : 0);
}

// order-preserving float <-> u32
__device__ __forceinline__ unsigned fmap(float x) {
    unsigned fb = __float_as_uint(x);
    return (fb & 0x80000000u) ? ~fb : (fb | 0x80000000u);
}
__device__ __forceinline__ float funmap(unsigned mu) {
    unsigned fb = (mu & 0x80000000u) ? (mu & 0x7FFFFFFFu) : ~mu;
    return __uint_as_float(fb);
}

// descending order: larger key first, then smaller idx first
__device__ __forceinline__ bool kv_gt(unsigned k1, unsigned p1, unsigned k2, unsigned p2) {
    return (k1 > k2) || (k1 == k2 && p1 < p2);
}
__device__ __forceinline__ void ce_sh(unsigned* kv, unsigned* pv, int i, int j, int K) {
    unsigned k1 = kv[i], p1 = pv[i], k2 = kv[i + j], p2 = pv[i + j];
    bool sw = ((i & K) == 0) ? kv_gt(k2, p2, k1, p1) : kv_gt(k1, p1, k2, p2);
    if (sw) { kv[i] = k2; pv[i] = p2; kv[i + j] = k1; pv[i + j] = p1; }
}

// ============================ ONE fused kernel ============================
__global__ void __launch_bounds__(NT) k_fused(const float* __restrict__ logits,
                                              const float* __restrict__ temps,
                                              const int*   __restrict__ top_ks,
                                              const float* __restrict__ top_ps,
                                              const float* __restrict__ min_ps,
                                              const float* __restrict__ u,
                                              float* __restrict__ out,
                                              int V, int B, int tokens_first)
{
    const int row = blockIdx.x;
    const int tid = threadIdx.x;
    const int lane = tid & 31, wid = tid >> 5;

    // 32 KB arena, phase-aliased (same layout as R9)
    __shared__ unsigned arena[8192];
    __shared__ float wred[32];
    __shared__ int   iwsum[32];
    __shared__ float s_S, s_shift, s_mx, s_lo;
    __shared__ int   s_bt, s_cnt, s_bad;
    __shared__ float sh_p0, sh_tot;

    int* hist = (int*)arena;

    float* probs_out = tokens_first ? (out + B) : out;
    float* prow = probs_out + (size_t)row * V;
    const float* lrow = logits + (size_t)row * V;
    const float invT = 1.0f / temps[row];
    const int need = V < 1024 ? V : 1024;
    const int V4 = V >> 2;
    const float4* l4 = (const float4*)lrow;

    // ---- Phase 0: zero this row's output (streaming stores drain under compute) ----
    if ((V & 3) == 0 && ((B & 3) == 0 || !tokens_first)) {
        float4* p4 = (float4*)prow;
        const float4 z4 = make_float4(0.f, 0.f, 0.f, 0.f);
        for (int i = tid; i < V4; i += NT) __stcs(p4 + i, z4);
    } else {
        for (int i = tid; i < V; i += NT) __stcs(prow + i, 0.f);
    }
    if (tid == 0) { s_cnt = 0; s_bad = 0; s_bt = 1024; }

    // ---- Phase 1: CONTIGUOUS-CHUNK 16k subsample histogram -> threshold ----
    // 4 chunks of 1024 consecutive float4 (16 KB each) at row quarters: reads
    // only 64 KB/row instead of strided sampling that touched every line.
    if (V > CAP) {
        for (int t = tid; t < NBINS; t += NT) hist[t] = 0;
        __syncthreads();
        int Vq = V4 >> 2; if (Vq < 1) Vq = 1;
        for (int k = tid; k < 4096; k += NT) {
            int c = k >> 10;
            int t = k & 1023;
            int pos = c * Vq + (t % Vq);
            if (pos >= V4) pos = V4 - 1;
            float4 v = l4[pos];
            if (v.x > 2.0f) atomicAdd(&hist[bin_of(v.x)], 1);
            if (v.y > 2.0f) atomicAdd(&hist[bin_of(v.y)], 1);
            if (v.z > 2.0f) atomicAdd(&hist[bin_of(v.z)], 1);
            if (v.w > 2.0f) atomicAdd(&hist[bin_of(v.w)], 1);
        }
        __syncthreads();
        // target expected true count ~1.55*need (>=4 sigma inside [1024, 2048])
        const int subN = 16384;
        int tgt = (int)(((long long)need * 31LL * subN) / (20LL * (long long)V));
        if (tgt < 1) tgt = 1;
        int b = 2047 - tid;
        int v = (tid < 960) ? hist[b] : 0;
        int sfx = block_incl_scan_int(v, iwsum, lane, wid);
        if (tid < 960 && sfx >= tgt && sfx - v < tgt) s_bt = b;
        __syncthreads();
    }
    const float xthr = (V > CAP) ? ((float)s_bt * 0.03125f - 32.0f) : -FLT_MAX;
    if (tid == 0) s_lo = xthr;
    __syncthreads();

    // ---- Phase 2: 4-way unrolled full pass: max + sum(__expf) + gather -> global ----
    #define GATHER4(vv, bi)                                                              \
        { _Pragma("unroll")                                                              \
          for (int c = 0; c < 4; c++) {                                                  \
            float x = (c == 0) ? (vv).x : (c == 1) ? (vv).y : (c == 2) ? (vv).z : (vv).w;\
            if (x >= xthr) {                                                             \
                int pos = atomicAdd(&s_cnt, 1);                                          \
                if (pos < CAP) { g_cval[row * CAP + pos] = x;                            \
                                 g_cidx[row * CAP + pos] = ((bi) << 2) + c; }            \
            } } }

    float sA = 0.f, sB = 0.f, sC = 0.f, sD = 0.f, mx = -FLT_MAX;
    int i = tid;
    for (; i + 3 * NT < V4; i += 4 * NT) {
        float4 va = l4[i];
        float4 vb = l4[i + NT];
        float4 vc = l4[i + 2 * NT];
        float4 vd = l4[i + 3 * NT];
        mx = fmaxf(mx, fmaxf(fmaxf(va.x, va.y), fmaxf(va.z, va.w)));
        mx = fmaxf(mx, fmaxf(fmaxf(vb.x, vb.y), fmaxf(vb.z, vb.w)));
        mx = fmaxf(mx, fmaxf(fmaxf(vc.x, vc.y), fmaxf(vc.z, vc.w)));
        mx = fmaxf(mx, fmaxf(fmaxf(vd.x, vd.y), fmaxf(vd.z, vd.w)));
        sA += __expf(va.x * invT) + __expf(va.y * invT) + __expf(va.z * invT) + __expf(va.w * invT);
        sB += __expf(vb.x * invT) + __expf(vb.y * invT) + __expf(vb.z * invT) + __expf(vb.w * invT);
        sC += __expf(vc.x * invT) + __expf(vc.y * invT) + __expf(vc.z * invT) + __expf(vc.w * invT);
        sD += __expf(vd.x * invT) + __expf(vd.y * invT) + __expf(vd.z * invT) + __expf(vd.w * invT);
        GATHER4(va, i);
        GATHER4(vb, i + NT);
        GATHER4(vc, i + 2 * NT);
        GATHER4(vd, i + 3 * NT);
    }
    for (; i < V4; i += NT) {
        float4 v = l4[i];
        mx = fmaxf(mx, fmaxf(fmaxf(v.x, v.y), fmaxf(v.z, v.w)));
        sA += __expf(v.x * invT) + __expf(v.y * invT) + __expf(v.z * invT) + __expf(v.w * invT);
        GATHER4(v, i);
    }
    float s = (sA + sB) + (sC + sD);
    for (int t = (V4 << 2) + tid; t < V; t += NT) {       // tail (V % 4)
        float x = lrow[t];
        mx = fmaxf(mx, x);
        s += __expf(x * invT);
        if (x >= xthr) {
            int pos = atomicAdd(&s_cnt, 1);
            if (pos < CAP) { g_cval[row * CAP + pos] = x; g_cidx[row * CAP + pos] = t; }
        }
    }
    #undef GATHER4

    // ---- Phase 3: reductions + overflow guard + verify/fallback ----
    s = warp_red_sum(s);
    if (lane == 0) wred[wid] = s;
    __syncthreads();
    if (wid == 0) { float t = warp_red_sum(wred[lane]); if (lane == 0) s_S = t; }
    __syncthreads();
    mx = warp_red_max(mx);
    if (lane == 0) wred[wid] = mx;
    __syncthreads();
    if (wid == 0) {
        float t = warp_red_max(wred[lane]);
        if (lane == 0) {
            s_mx = t;
            float mxT = t * invT;
            s_shift = (mxT > 80.f || !isfinite(s_S)) ? mxT : 0.f;
        }
    }
    __syncthreads();
    const float shift = s_shift;
    if (shift != 0.f) {        // rare overflow-safe recompute (precise path)
        s = 0.f;
        for (int t = tid; t < V; t += NT) s += expf(lrow[t] * invT - shift);
        s = warp_red_sum(s);
        if (lane == 0) wred[wid] = s;
        __syncthreads();
        if (wid == 0) { float t = warp_red_sum(wred[lane]); if (lane == 0) s_S = t; }
        __syncthreads();
    }

    int C = s_cnt;
    if (V > CAP && !(C >= need && C <= CAP)) {
        // FALLBACK (~never): exact coarse histogram -> guaranteed threshold -> regather
        for (int t = tid; t < NBINS; t += NT) hist[t] = 0;
        __syncthreads();
        for (int t = tid; t < V; t += NT) atomicAdd(&hist[bin_of(lrow[t])], 1);
        __syncthreads();
        if (tid == 0) {
            int acc = 0, bt2 = 0;
            for (int b = NBINS - 1; b >= 0; b--) {
                int na = acc + hist[b];
                if (na >= need) { bt2 = (na <= CAP) ? b : (b + 1); break; }
                acc = na;
            }
            s_bt = bt2; s_cnt = 0;
            s_lo = (float)bt2 * 0.03125f - 32.0f - 0.0625f;   // safe lower bound
        }
        __syncthreads();
        const int bt2 = s_bt;
        for (int t = tid; t < V; t += NT) {
            float x = lrow[t];
            if (bin_of(x) >= bt2) {
                int pos = atomicAdd(&s_cnt, 1);
                if (pos < CAP) { g_cval[row * CAP + pos] = x; g_cidx[row * CAP + pos] = t; }
            }
        }
        __syncthreads();
        C = s_cnt;
    }
    C = C < CAP ? C : CAP;
    __syncthreads();

    // ---- Phase 4: histogram ranking ----
    const float lo = s_lo, hi = s_mx;
    const float range = hi - lo;
    int*      bins = (int*)arena;
    unsigned* skv  = arena + 4096;
    unsigned* skp  = arena + 6144;
    unsigned *pk = skv, *pp = skp;

    bool fast = (C <= 2048) && (range > 0.f) && isfinite(range);

    if (fast) {
        const float scale = (float)FB / range;
        unsigned k0 = 0, k1 = 0; int i0 = 0, i1 = 0, b0 = 0, b1 = 0;
        float x0 = 0.f, x1 = 0.f;
        if (tid < C)        { x0 = g_cval[row * CAP + tid];        i0 = g_cidx[row * CAP + tid];        k0 = fmap(x0); }
        if (tid + 1024 < C) { x1 = g_cval[row * CAP + tid + 1024]; i1 = g_cidx[row * CAP + tid + 1024]; k1 = fmap(x1); }
        #pragma unroll
        for (int t = 0; t < 4; t++) bins[tid + t * NT] = 0;
        __syncthreads();
        if (tid < C) {
            b0 = (int)((x0 - lo) * scale); b0 = b0 < 0 ? 0 : (b0 > FB - 1 ? FB - 1 : b0);
            atomicAdd(&bins[b0], 1);
        }
        if (tid + 1024 < C) {
            b1 = (int)((x1 - lo) * scale); b1 = b1 < 0 ? 0 : (b1 > FB - 1 ? FB - 1 : b1);
            atomicAdd(&bins[b1], 1);
        }
        __syncthreads();
        // suffix scan in descending-bin order; thread t owns bins 4095-4t..4092-4t
        int c0c = bins[4095 - 4 * tid];
        int c1c = bins[4094 - 4 * tid];
        int c2c = bins[4093 - 4 * tid];
        int c3c = bins[4092 - 4 * tid];
        int tot4 = c0c + c1c + c2c + c3c;
        int base = block_incl_scan_int(tot4, iwsum, lane, wid) - tot4;
        bins[4095 - 4 * tid] = base;
        bins[4094 - 4 * tid] = base + c0c;
        bins[4093 - 4 * tid] = base + c0c + c1c;
        bins[4092 - 4 * tid] = base + c0c + c1c + c2c;
        __syncthreads();
        if (tid < C)        { int sl = atomicAdd(&bins[b0], 1); skv[sl] = k0; skp[sl] = (unsigned)i0; }
        if (tid + 1024 < C) { int sl = atomicAdd(&bins[b1], 1); skv[sl] = k1; skp[sl] = (unsigned)i1; }
        __syncthreads();
        // fixup within-bin order: insertion sort on contiguous same-bin runs
        #pragma unroll
        for (int e = 0; e < 2; e++) {
            int ii = tid + e * 1024;
            if (ii < C) {
                int bi = (int)((funmap(skv[ii]) - lo) * scale); bi = bi < 0 ? 0 : (bi > FB - 1 ? FB - 1 : bi);
                int bp = -1;
                if (ii > 0) {
                    bp = (int)((funmap(skv[ii - 1]) - lo) * scale); bp = bp < 0 ? 0 : (bp > FB - 1 ? FB - 1 : bp);
                }
                if (bi != bp) {                       // run start
                    int L = 1;
                    while (ii + L < C && L <= 16) {
                        int bn = (int)((funmap(skv[ii + L]) - lo) * scale); bn = bn < 0 ? 0 : (bn > FB - 1 ? FB - 1 : bn);
                        if (bn != bi) break;
                        L++;
                    }
                    if (L > 16) { atomicExch(&s_bad, 1); }
                    else if (L > 1) {
                        unsigned lk[16], lp[16];
                        for (int t = 0; t < L; t++) { lk[t] = skv[ii + t]; lp[t] = skp[ii + t]; }
                        for (int a = 1; a < L; a++) {
                            unsigned ck = lk[a], cp = lp[a];
                            int b2 = a - 1;
                            while (b2 >= 0 && !kv_gt(lk[b2], lp[b2], ck, cp)) {
                                lk[b2 + 1] = lk[b2]; lp[b2 + 1] = lp[b2]; b2--;
                            }
                            lk[b2 + 1] = ck; lp[b2 + 1] = cp;
                        }
                        for (int t = 0; t < L; t++) { skv[ii + t] = lk[t]; skp[ii + t] = lp[t]; }
                    }
                }
            }
        }
        __syncthreads();
        if (s_bad) fast = false;
        __syncthreads();
    }

    if (!fast) {
        // exact bitonic on 4096 (rare)
        unsigned* fkv = arena;
        unsigned* fkp = arena + 4096;
        for (int ii = tid; ii < CAP; ii += NT) {
            unsigned key = 0u, pay = 0xFFFFFFFFu;
            if (ii < C) { key = fmap(g_cval[row * CAP + ii]); pay = (unsigned)g_cidx[row * CAP + ii]; }
            fkv[ii] = key; fkp[ii] = pay;
        }
        __syncthreads();
        for (int K = 2; K <= CAP; K <<= 1) {
            int j = K >> 1;
            for (; j >= 64; j >>= 1) {
                for (int c = tid; c < (CAP >> 1); c += NT) {
                    int ii = ((c & ~(j - 1)) << 1) | (c & (j - 1));
                    ce_sh(fkv, fkp, ii, j, K);
                }
                __syncthreads();
            }
            for (; j >= 1; j >>= 1) {
                for (int c = tid; c < (CAP >> 1); c += NT) {
                    int ii = ((c & ~(j - 1)) << 1) | (c & (j - 1));
                    ce_sh(fkv, fkp, ii, j, K);
                }
                __syncwarp();
            }
            __syncthreads();
        }
        pk = fkv; pp = fkp;
    }

    // ---- Phase 5: masks (reference order) + inverse-CDF sample + scatter ----
    const float S = s_S;
    float p = 0.f;
    int   myidx = 0;
    if (tid < C) {
        p = expf(funmap(pk[tid]) * invT - shift) / S;
        myidx = (int)pp[tid];
    }
    if (tid == 0) sh_p0 = p;

    float cumincl = block_incl_scan(p, wred, lane, wid);   // pre-mask cumsum

    const int   tk  = top_ks[row];
    const float tp  = top_ps[row];
    const float thr = sh_p0 * min_ps[row];
    float q = p;
    if (tid >= tk)        q = 0.f;   // top-k
    if (cumincl - q > tp) q = 0.f;   // top-p (cumsum computed pre-mask)
    if (q < thr)          q = 0.f;   // min-p

    float cq = block_incl_scan(q, wred, lane, wid);        // post-mask CDF numerator
    if (tid == NT - 1) sh_tot = cq;
    __syncthreads();
    const float tot  = sh_tot;
    const float uval = u[row];

    int rank = __syncthreads_count((cq / tot < uval) ? 1 : 0);
    if (rank > NT - 1) rank = NT - 1;
    if (rank > V - 1) rank = V - 1;

    if (tid == 0 && tokens_first) {
        out[row] = (float)(int)pp[rank];
    }
    if (q > 0.f) {
        prow[myidx] = q / tot;   // ordered after phase-0 zero stores by barriers
    }
}

extern "C" void kernel_launch(void* const* d_in, const int* in_sizes, int n_in,
                              void* d_out, int out_size)
{
    const float* logits = (const float*)d_in[0];
    const float* temps  = (const float*)d_in[1];
    const int*   topks  = (const int*)  d_in[2];
    const float* topps  = (const float*)d_in[3];
    const float* minps  = (const float*)d_in[4];
    const float* u      = (const float*)d_in[5];

    const int B = in_sizes[1];
    const int V = in_sizes[0] / B;
    float* out = (float*)d_out;
    int tokens_first = (out_size == B + B * V) ? 1 : 0;

    k_fused<<<B, NT>>>(logits, temps, topks, topps, minps, u, out, V, B, tokens_first);
}

// round 12
// speedup vs baseline: 1.9371x; 1.0288x over previous
#include <cuda_runtime.h>
#include <math.h>
#include <stdint.h>
#include <float.h>

#define MAXB  128
#define CAP   4096
#define NBINS 2048     // coarse subsample bins
#define FB    4096     // fine ranking bins
#define NT    1024
#define WSEG  128      // per-warp candidate segment (32 warps * 128 = CAP)

// Global candidate staging (written phase 2/3, read phase 4)
__device__ float g_cval[MAXB * CAP];
__device__ int   g_cidx[MAXB * CAP];

__device__ __forceinline__ int bin_of(float x) {
    int b = (int)floorf((x + 32.0f) * 32.0f);   // width 1/32 over [-32, 32]
    b = b < 0 ? 0 : b;
    return b > (NBINS - 1) ? (NBINS - 1) : b;
}

__device__ __forceinline__ float warp_red_sum(float v) {
    #pragma unroll
    for (int o = 16; o; o >>= 1) v += __shfl_xor_sync(0xffffffffu, v, o);
    return v;
}
__device__ __forceinline__ float warp_red_max(float v) {
    #pragma unroll
    for (int o = 16; o; o >>= 1) v = fmaxf(v, __shfl_xor_sync(0xffffffffu, v, o));
    return v;
}

__device__ __forceinline__ float block_incl_scan(float v, float* wsum, int lane, int wid) {
    #pragma unroll
    for (int off = 1; off < 32; off <<= 1) {
        float n = __shfl_up_sync(0xffffffffu, v, off);
        if (lane >= off) v += n;
    }
    __syncthreads();
    if (lane == 31) wsum[wid] = v;
    __syncthreads();
    if (wid == 0) {
        float w = wsum[lane];
        #pragma unroll
        for (int off = 1; off < 32; off <<= 1) {
            float n = __shfl_up_sync(0xffffffffu, w, off);
            if (lane >= off) w += n;
        }
        wsum[lane] = w;
    }
    __syncthreads();
    return v + (wid ? wsum[wid - 1] : 0.f);
}

__device__ __forceinline__ int block_incl_scan_int(int v, int* wsum, int lane, int wid) {
    #pragma unroll
    for (int off = 1; off < 32; off <<= 1) {
        int n = __shfl_up_sync(0xffffffffu, v, off);
        if (lane >= off) v += n;
    }
    __syncthreads();
    if (lane == 31) wsum[wid] = v;
    __syncthreads();
    if (wid == 0) {
        int w = wsum[lane];
        #pragma unroll
        for (int off = 1; off < 32; off <<= 1) {
            int n = __shfl_up_sync(0xffffffffu, w, off);
            if (lane >= off) w += n;
        }
        wsum[lane] = w;
    }
    __syncthreads();
    return v + (wid ? wsum[wid - 1] : 0);
}

// order-preserving float <-> u32
__device__ __forceinline__ unsigned fmap(float x) {
    unsigned fb = __float_as_uint(x);
    return (fb & 0x80000000u) ? ~fb : (fb | 0x80000000u);
}
__device__ __forceinline__ float funmap(unsigned mu) {
    unsigned fb = (mu & 0x80000000u) ? (mu & 0x7FFFFFFFu) : ~mu;
    return __uint_as_float(fb);
}

// descending order: larger key first, then smaller idx first
__device__ __forceinline__ bool kv_gt(unsigned k1, unsigned p1, unsigned k2, unsigned p2) {
    return (k1 > k2) || (k1 == k2 && p1 < p2);
}
__device__ __forceinline__ void ce_sh(unsigned* kv, unsigned* pv, int i, int j, int K) {
    unsigned k1 = kv[i], p1 = pv[i], k2 = kv[i + j], p2 = pv[i + j];
    bool sw = ((i & K) == 0) ? kv_gt(k2, p2, k1, p1) : kv_gt(k1, p1, k2, p2);
    if (sw) { kv[i] = k2; pv[i] = p2; kv[i + j] = k1; pv[i + j] = p1; }
}

// ============================ ONE fused kernel ============================
__global__ void __launch_bounds__(NT) k_fused(const float* __restrict__ logits,
                                              const float* __restrict__ temps,
                                              const int*   __restrict__ top_ks,
                                              const float* __restrict__ top_ps,
                                              const float* __restrict__ min_ps,
                                              const float* __restrict__ u,
                                              float* __restrict__ out,
                                              int V, int B, int tokens_first)
{
    const int row = blockIdx.x;
    const int tid = threadIdx.x;
    const int lane = tid & 31, wid = tid >> 5;
    const unsigned lmlt = (1u << lane) - 1u;

    __shared__ unsigned arena[8192];       // 32 KB phase-aliased
    __shared__ float wred[32];
    __shared__ int   iwsum[32];
    __shared__ int   scnt[32];             // per-warp candidate counts
    __shared__ float s_S, s_shift, s_mx, s_lo;
    __shared__ int   s_bt, s_cnt, s_bad, s_ovf;
    __shared__ float sh_p0, sh_tot;

    int* hist = (int*)arena;

    float* probs_out = tokens_first ? (out + B) : out;
    float* prow = probs_out + (size_t)row * V;
    const float* lrow = logits + (size_t)row * V;
    const float invT = 1.0f / temps[row];
    const int need = V < 1024 ? V : 1024;
    const int V4 = V >> 2;
    const float4* l4 = (const float4*)lrow;

    // ---- Phase 0: zero this row's output (streaming stores drain under compute) ----
    if ((V & 3) == 0 && ((B & 3) == 0 || !tokens_first)) {
        float4* p4 = (float4*)prow;
        const float4 z4 = make_float4(0.f, 0.f, 0.f, 0.f);
        for (int i = tid; i < V4; i += NT) __stcs(p4 + i, z4);
    } else {
        for (int i = tid; i < V; i += NT) __stcs(prow + i, 0.f);
    }
    if (tid == 0) { s_cnt = 0; s_bad = 0; s_ovf = 0; s_bt = 1024; }

    // ---- Phase 1: contiguous-chunk 16k subsample histogram -> threshold ----
    if (V > CAP) {
        for (int t = tid; t < NBINS; t += NT) hist[t] = 0;
        __syncthreads();
        int Vq = V4 >> 2; if (Vq < 1) Vq = 1;
        for (int k = tid; k < 4096; k += NT) {
            int c = k >> 10;
            int t = k & 1023;
            int pos = c * Vq + (t % Vq);
            if (pos >= V4) pos = V4 - 1;
            float4 v = l4[pos];
            if (v.x > 2.0f) atomicAdd(&hist[bin_of(v.x)], 1);
            if (v.y > 2.0f) atomicAdd(&hist[bin_of(v.y)], 1);
            if (v.z > 2.0f) atomicAdd(&hist[bin_of(v.z)], 1);
            if (v.w > 2.0f) atomicAdd(&hist[bin_of(v.w)], 1);
        }
        __syncthreads();
        const int subN = 16384;
        int tgt = (int)(((long long)need * 31LL * subN) / (20LL * (long long)V));
        if (tgt < 1) tgt = 1;
        int b = 2047 - tid;
        int v = (tid < 960) ? hist[b] : 0;
        int sfx = block_incl_scan_int(v, iwsum, lane, wid);
        if (tid < 960 && sfx >= tgt && sfx - v < tgt) s_bt = b;
        __syncthreads();
    }
    const float xthr = (V > CAP) ? ((float)s_bt * 0.03125f - 32.0f) : -FLT_MAX;
    if (tid == 0) s_lo = xthr;
    __syncthreads();

    // ---- Phase 2: 4-way unrolled pass: max + sum(__expf) + ATOMIC-FREE gather ----
    // Each warp owns g_cval[row*CAP + wid*WSEG .. +WSEG): ballot+popc position,
    // predicated store, count in a register. No shared atomics on the hot path.
    const int wbase = row * CAP + wid * WSEG;
    int wcnt = 0;

    #define GATHER4(vv, bi)                                                              \
        { _Pragma("unroll")                                                              \
          for (int c = 0; c < 4; c++) {                                                  \
            float x = (c == 0) ? (vv).x : (c == 1) ? (vv).y : (c == 2) ? (vv).z : (vv).w;\
            bool pred = (x >= xthr);                                                     \
            unsigned m = __ballot_sync(0xffffffffu, pred);                               \
            int pos = wcnt + __popc(m & lmlt);                                           \
            if (pred && pos < WSEG) { g_cval[wbase + pos] = x;                           \
                                      g_cidx[wbase + pos] = ((bi) << 2) + c; }           \
            wcnt += __popc(m); }                                                         \
        }

    float sA = 0.f, sB = 0.f, sC = 0.f, sD = 0.f, mx = -FLT_MAX;
    int i = tid;
    for (; i + 3 * NT < V4; i += 4 * NT) {
        float4 va = l4[i];
        float4 vb = l4[i + NT];
        float4 vc = l4[i + 2 * NT];
        float4 vd = l4[i + 3 * NT];
        mx = fmaxf(mx, fmaxf(fmaxf(va.x, va.y), fmaxf(va.z, va.w)));
        mx = fmaxf(mx, fmaxf(fmaxf(vb.x, vb.y), fmaxf(vb.z, vb.w)));
        mx = fmaxf(mx, fmaxf(fmaxf(vc.x, vc.y), fmaxf(vc.z, vc.w)));
        mx = fmaxf(mx, fmaxf(fmaxf(vd.x, vd.y), fmaxf(vd.z, vd.w)));
        sA += __expf(va.x * invT) + __expf(va.y * invT) + __expf(va.z * invT) + __expf(va.w * invT);
        sB += __expf(vb.x * invT) + __expf(vb.y * invT) + __expf(vb.z * invT) + __expf(vb.w * invT);
        sC += __expf(vc.x * invT) + __expf(vc.y * invT) + __expf(vc.z * invT) + __expf(vc.w * invT);
        sD += __expf(vd.x * invT) + __expf(vd.y * invT) + __expf(vd.z * invT) + __expf(vd.w * invT);
        GATHER4(va, i);
        GATHER4(vb, i + NT);
        GATHER4(vc, i + 2 * NT);
        GATHER4(vd, i + 3 * NT);
    }
    for (; i < V4; i += NT) {        // V4 multiple of NT here; safe: whole warps iterate
        float4 v = l4[i];
        mx = fmaxf(mx, fmaxf(fmaxf(v.x, v.y), fmaxf(v.z, v.w)));
        sA += __expf(v.x * invT) + __expf(v.y * invT) + __expf(v.z * invT) + __expf(v.w * invT);
        GATHER4(v, i);
    }
    #undef GATHER4
    float s = (sA + sB) + (sC + sD);
    // tail (V % 4): whole-warp iteration with bounds predication (ballot-safe)
    for (int t = (V4 << 2) + tid; t - lane < V; t += NT) {
        bool in = t < V;
        float x = in ? lrow[t] : -FLT_MAX;
        if (in) { mx = fmaxf(mx, x); s += __expf(x * invT); }
        bool pred = in && (x >= xthr);
        unsigned m = __ballot_sync(0xffffffffu, pred);
        int pos = wcnt + __popc(m & lmlt);
        if (pred && pos < WSEG) { g_cval[wbase + pos] = x; g_cidx[wbase + pos] = t; }
        wcnt += __popc(m);
    }
    if (lane == 0) scnt[wid] = wcnt;
    if (wcnt > WSEG && lane == 0) atomicExch(&s_ovf, 1);

    // ---- Phase 3: reductions + overflow guard + verify ----
    s = warp_red_sum(s);
    if (lane == 0) wred[wid] = s;
    __syncthreads();
    if (wid == 0) { float t = warp_red_sum(wred[lane]); if (lane == 0) s_S = t; }
    __syncthreads();
    mx = warp_red_max(mx);
    if (lane == 0) wred[wid] = mx;
    __syncthreads();
    if (wid == 0) {
        float t = warp_red_max(wred[lane]);
        if (lane == 0) {
            s_mx = t;
            float mxT = t * invT;
            s_shift = (mxT > 80.f || !isfinite(s_S)) ? mxT : 0.f;
        }
    }
    __syncthreads();
    const float shift = s_shift;
    if (shift != 0.f) {        // rare overflow-safe recompute (precise path)
        s = 0.f;
        for (int t = tid; t < V; t += NT) s += expf(lrow[t] * invT - shift);
        s = warp_red_sum(s);
        if (lane == 0) wred[wid] = s;
        __syncthreads();
        if (wid == 0) { float t = warp_red_sum(wred[lane]); if (lane == 0) s_S = t; }
        __syncthreads();
    }

    // total candidate count
    if (wid == 0) {
        int c = scnt[lane];
        #pragma unroll
        for (int o = 16; o; o >>= 1) c += __shfl_xor_sync(0xffffffffu, c, o);
        if (lane == 0) s_cnt = c;
    }
    __syncthreads();
    int C = s_cnt;
    bool segmented = (V > CAP);
    bool bad = segmented && (s_ovf || !(C >= need && C <= 2048));

    if ((V > CAP && bad) || V <= CAP) {
        // FALLBACK path: exact coarse histogram -> contiguous re-gather (rare),
        // or small-V direct copy. Produces contiguous g_cval[row*CAP + 0..C).
        segmented = false;
        if (V <= CAP) {
            for (int t = tid; t < V; t += NT) { g_cval[row * CAP + t] = lrow[t]; g_cidx[row * CAP + t] = t; }
            if (tid == 0) s_cnt = V;
            __syncthreads();
        } else {
            for (int t = tid; t < NBINS; t += NT) hist[t] = 0;
            __syncthreads();
            for (int t = tid; t < V; t += NT) atomicAdd(&hist[bin_of(lrow[t])], 1);
            __syncthreads();
            if (tid == 0) {
                int acc = 0, bt2 = 0;
                for (int b = NBINS - 1; b >= 0; b--) {
                    int na = acc + hist[b];
                    if (na >= need) { bt2 = (na <= CAP) ? b : (b + 1); break; }
                    acc = na;
                }
                s_bt = bt2; s_cnt = 0;
                s_lo = (float)bt2 * 0.03125f - 32.0f - 0.0625f;
            }
            __syncthreads();
            const int bt2 = s_bt;
            for (int t = tid; t < V; t += NT) {
                float x = lrow[t];
                if (bin_of(x) >= bt2) {
                    int pos = atomicAdd(&s_cnt, 1);
                    if (pos < CAP) { g_cval[row * CAP + pos] = x; g_cidx[row * CAP + pos] = t; }
                }
            }
            __syncthreads();
        }
        C = s_cnt;
    }
    C = C < CAP ? C : CAP;
    __syncthreads();

    // ---- Phase 4: histogram ranking over 4 segmented slots per thread ----
    const float lo = s_lo, hi = s_mx;
    const float range = hi - lo;
    int*      bins = (int*)arena;
    unsigned* skv  = arena + 4096;
    unsigned* skp  = arena + 6144;
    unsigned *pk = skv, *pp = skp;

    bool fast = segmented && (C <= 2048) && (range > 0.f) && isfinite(range);

    if (fast) {
        const float scale = (float)FB / range;
        float    xv[4];
        int      xi[4], xb[4];
        bool     val[4];
        #pragma unroll
        for (int e = 0; e < 4; e++) {
            int slot = tid + e * NT;                // 0..4095
            int w = slot >> 7, j = slot & (WSEG - 1);
            val[e] = j < scnt[w];
            if (val[e]) { xv[e] = g_cval[row * CAP + slot]; xi[e] = g_cidx[row * CAP + slot]; }
        }
        #pragma unroll
        for (int t = 0; t < 4; t++) bins[tid + t * NT] = 0;
        __syncthreads();
        #pragma unroll
        for (int e = 0; e < 4; e++) {
            if (val[e]) {
                int b = (int)((xv[e] - lo) * scale); b = b < 0 ? 0 : (b > FB - 1 ? FB - 1 : b);
                xb[e] = b;
                atomicAdd(&bins[b], 1);
            }
        }
        __syncthreads();
        int c0c = bins[4095 - 4 * tid];
        int c1c = bins[4094 - 4 * tid];
        int c2c = bins[4093 - 4 * tid];
        int c3c = bins[4092 - 4 * tid];
        int tot4 = c0c + c1c + c2c + c3c;
        int base = block_incl_scan_int(tot4, iwsum, lane, wid) - tot4;
        bins[4095 - 4 * tid] = base;
        bins[4094 - 4 * tid] = base + c0c;
        bins[4093 - 4 * tid] = base + c0c + c1c;
        bins[4092 - 4 * tid] = base + c0c + c1c + c2c;
        __syncthreads();
        #pragma unroll
        for (int e = 0; e < 4; e++) {
            if (val[e]) {
                int sl = atomicAdd(&bins[xb[e]], 1);
                skv[sl] = fmap(xv[e]); skp[sl] = (unsigned)xi[e];
            }
        }
        __syncthreads();
        // fixup within-bin order: insertion sort on contiguous same-bin runs
        #pragma unroll
        for (int e = 0; e < 2; e++) {
            int ii = tid + e * 1024;
            if (ii < C) {
                int bi = (int)((funmap(skv[ii]) - lo) * scale); bi = bi < 0 ? 0 : (bi > FB - 1 ? FB - 1 : bi);
                int bp = -1;
                if (ii > 0) {
                    bp = (int)((funmap(skv[ii - 1]) - lo) * scale); bp = bp < 0 ? 0 : (bp > FB - 1 ? FB - 1 : bp);
                }
                if (bi != bp) {                       // run start
                    int L = 1;
                    while (ii + L < C && L <= 16) {
                        int bn = (int)((funmap(skv[ii + L]) - lo) * scale); bn = bn < 0 ? 0 : (bn > FB - 1 ? FB - 1 : bn);
                        if (bn != bi) break;
                        L++;
                    }
                    if (L > 16) { atomicExch(&s_bad, 1); }
                    else if (L > 1) {
                        unsigned lk[16], lp[16];
                        for (int t = 0; t < L; t++) { lk[t] = skv[ii + t]; lp[t] = skp[ii + t]; }
                        for (int a = 1; a < L; a++) {
                            unsigned ck = lk[a], cp = lp[a];
                            int b2 = a - 1;
                            while (b2 >= 0 && !kv_gt(lk[b2], lp[b2], ck, cp)) {
                                lk[b2 + 1] = lk[b2]; lp[b2 + 1] = lp[b2]; b2--;
                            }
                            lk[b2 + 1] = ck; lp[b2 + 1] = cp;
                        }
                        for (int t = 0; t < L; t++) { skv[ii + t] = lk[t]; skp[ii + t] = lp[t]; }
                    }
                }
            }
        }
        __syncthreads();
        if (s_bad) fast = false;
        __syncthreads();
    }

    if (!fast) {
        // exact bitonic on 4096 (rare). Needs contiguous candidates: compact first
        // if still segmented.
        if (segmented) {
            // compact segments into shared, then write back contiguous
            unsigned* ckv = arena;          // 4096
            unsigned* ckp = arena + 4096;   // 4096
            // per-warp exclusive base via scan of scnt
            if (wid == 0) {
                int c = (lane < 32) ? scnt[lane] : 0;
                int inc = c;
                #pragma unroll
                for (int off = 1; off < 32; off <<= 1) {
                    int n = __shfl_up_sync(0xffffffffu, inc, off);
                    if (lane >= off) inc += n;
                }
                iwsum[lane] = inc - c;      // exclusive base per warp
            }
            __syncthreads();
            #pragma unroll
            for (int e = 0; e < 4; e++) {
                int slot = tid + e * NT;
                int w = slot >> 7, j = slot & (WSEG - 1);
                if (j < scnt[w]) {
                    int dst = iwsum[w] + j;
                    ckv[dst] = fmap(g_cval[row * CAP + slot]);
                    ckp[dst] = (unsigned)g_cidx[row * CAP + slot];
                }
            }
            __syncthreads();
            for (int ii = tid; ii < CAP; ii += NT) {
                if (ii >= C) { ckv[ii] = 0u; ckp[ii] = 0xFFFFFFFFu; }
            }
            __syncthreads();
        } else {
            unsigned* ckv = arena;
            unsigned* ckp = arena + 4096;
            for (int ii = tid; ii < CAP; ii += NT) {
                unsigned key = 0u, pay = 0xFFFFFFFFu;
                if (ii < C) { key = fmap(g_cval[row * CAP + ii]); pay = (unsigned)g_cidx[row * CAP + ii]; }
                ckv[ii] = key; ckp[ii] = pay;
            }
            __syncthreads();
        }
        unsigned* fkv = arena;
        unsigned* fkp = arena + 4096;
        for (int K = 2; K <= CAP; K <<= 1) {
            int j = K >> 1;
            for (; j >= 64; j >>= 1) {
                for (int c = tid; c < (CAP >> 1); c += NT) {
                    int ii = ((c & ~(j - 1)) << 1) | (c & (j - 1));
                    ce_sh(fkv, fkp, ii, j, K);
                }
                __syncthreads();
            }
            for (; j >= 1; j >>= 1) {
                for (int c = tid; c < (CAP >> 1); c += NT) {
                    int ii = ((c & ~(j - 1)) << 1) | (c & (j - 1));
                    ce_sh(fkv, fkp, ii, j, K);
                }
                __syncwarp();
            }
            __syncthreads();
        }
        pk = fkv; pp = fkp;
    }

    // ---- Phase 5: masks (reference order) + inverse-CDF sample + scatter ----
    const float S = s_S;
    float p = 0.f;
    int   myidx = 0;
    if (tid < C) {
        p = expf(funmap(pk[tid]) * invT - shift) / S;
        myidx = (int)pp[tid];
    }
    if (tid == 0) sh_p0 = p;

    float cumincl = block_incl_scan(p, wred, lane, wid);   // pre-mask cumsum

    const int   tk  = top_ks[row];
    const float tp  = top_ps[row];
    const float thr = sh_p0 * min_ps[row];
    float q = p;
    if (tid >= tk)        q = 0.f;   // top-k
    if (cumincl - q > tp) q = 0.f;   // top-p (cumsum computed pre-mask)
    if (q < thr)          q = 0.f;   // min-p

    float cq = block_incl_scan(q, wred, lane, wid);        // post-mask CDF numerator
    if (tid == NT - 1) sh_tot = cq;
    __syncthreads();
    const float tot  = sh_tot;
    const float uval = u[row];

    int rank = __syncthreads_count((cq / tot < uval) ? 1 : 0);
    if (rank > NT - 1) rank = NT - 1;
    if (rank > V - 1) rank = V - 1;

    if (tid == 0 && tokens_first) {
        out[row] = (float)(int)pp[rank];
    }
    if (q > 0.f) {
        prow[myidx] = q / tot;   // ordered after phase-0 zero stores by barriers
    }
}

extern "C" void kernel_launch(void* const* d_in, const int* in_sizes, int n_in,
                              void* d_out, int out_size)
{
    const float* logits = (const float*)d_in[0];
    const float* temps  = (const float*)d_in[1];
    const int*   topks  = (const int*)  d_in[2];
    const float* topps  = (const float*)d_in[3];
    const float* minps  = (const float*)d_in[4];
    const float* u      = (const float*)d_in[5];

    const int B = in_sizes[1];
    const int V = in_sizes[0] / B;
    float* out = (float*)d_out;
    int tokens_first = (out_size == B + B * V) ? 1 : 0;

    k_fused<<<B, NT>>>(logits, temps, topks, topps, minps, u, out, V, B, tokens_first);
}

// round 13
// speedup vs baseline: 2.1516x; 1.1107x over previous
#include <cuda_runtime.h>
#include <math.h>
#include <stdint.h>
#include <float.h>

#define MAXB  128
#define CAP   4096
#define NBINS 2048     // coarse subsample bins
#define FB    4096     // fine ranking bins
#define NT    1024
#define WSEG  128      // per-warp candidate segment (32 warps * 128 = CAP)

// Global candidate staging (written phase 2/3, read phase 4)
__device__ float g_cval[MAXB * CAP];
__device__ int   g_cidx[MAXB * CAP];

__device__ __forceinline__ int bin_of(float x) {
    int b = (int)floorf((x + 32.0f) * 32.0f);   // width 1/32 over [-32, 32]
    b = b < 0 ? 0 : b;
    return b > (NBINS - 1) ? (NBINS - 1) : b;
}

__device__ __forceinline__ float warp_red_sum(float v) {
    #pragma unroll
    for (int o = 16; o; o >>= 1) v += __shfl_xor_sync(0xffffffffu, v, o);
    return v;
}
__device__ __forceinline__ float warp_red_max(float v) {
    #pragma unroll
    for (int o = 16; o; o >>= 1) v = fmaxf(v, __shfl_xor_sync(0xffffffffu, v, o));
    return v;
}

__device__ __forceinline__ float block_incl_scan(float v, float* wsum, int lane, int wid) {
    #pragma unroll
    for (int off = 1; off < 32; off <<= 1) {
        float n = __shfl_up_sync(0xffffffffu, v, off);
        if (lane >= off) v += n;
    }
    __syncthreads();
    if (lane == 31) wsum[wid] = v;
    __syncthreads();
    if (wid == 0) {
        float w = wsum[lane];
        #pragma unroll
        for (int off = 1; off < 32; off <<= 1) {
            float n = __shfl_up_sync(0xffffffffu, w, off);
            if (lane >= off) w += n;
        }
        wsum[lane] = w;
    }
    __syncthreads();
    return v + (wid ? wsum[wid - 1] : 0.f);
}

__device__ __forceinline__ int block_incl_scan_int(int v, int* wsum, int lane, int wid) {
    #pragma unroll
    for (int off = 1; off < 32; off <<= 1) {
        int n = __shfl_up_sync(0xffffffffu, v, off);
        if (lane >= off) v += n;
    }
    __syncthreads();
    if (lane == 31) wsum[wid] = v;
    __syncthreads();
    if (wid == 0) {
        int w = wsum[lane];
        #pragma unroll
        for (int off = 1; off < 32; off <<= 1) {
            int n = __shfl_up_sync(0xffffffffu, w, off);
            if (lane >= off) w += n;
        }
        wsum[lane] = w;
    }
    __syncthreads();
    return v + (wid ? wsum[wid - 1] : 0);
}

// order-preserving float <-> u32
__device__ __forceinline__ unsigned fmap(float x) {
    unsigned fb = __float_as_uint(x);
    return (fb & 0x80000000u) ? ~fb : (fb | 0x80000000u);
}
__device__ __forceinline__ float funmap(unsigned mu) {
    unsigned fb = (mu & 0x80000000u) ? (mu & 0x7FFFFFFFu) : ~mu;
    return __uint_as_float(fb);
}

// descending order: larger key first, then smaller idx first
__device__ __forceinline__ bool kv_gt(unsigned k1, unsigned p1, unsigned k2, unsigned p2) {
    return (k1 > k2) || (k1 == k2 && p1 < p2);
}
__device__ __forceinline__ void ce_sh(unsigned* kv, unsigned* pv, int i, int j, int K) {
    unsigned k1 = kv[i], p1 = pv[i], k2 = kv[i + j], p2 = pv[i + j];
    bool sw = ((i & K) == 0) ? kv_gt(k2, p2, k1, p1) : kv_gt(k1, p1, k2, p2);
    if (sw) { kv[i] = k2; pv[i] = p2; kv[i + j] = k1; pv[i + j] = p1; }
}

// ============================ ONE fused kernel ============================
__global__ void __launch_bounds__(NT) k_fused(const float* __restrict__ logits,
                                              const float* __restrict__ temps,
                                              const int*   __restrict__ top_ks,
                                              const float* __restrict__ top_ps,
                                              const float* __restrict__ min_ps,
                                              const float* __restrict__ u,
                                              float* __restrict__ out,
                                              int V, int B, int tokens_first)
{
    const int row = blockIdx.x;
    const int tid = threadIdx.x;
    const int lane = tid & 31, wid = tid >> 5;
    const unsigned lmlt = (1u << lane) - 1u;

    __shared__ unsigned arena[8192];       // 32 KB phase-aliased
    __shared__ float wred[32];
    __shared__ int   iwsum[32];
    __shared__ int   scnt[32];             // per-warp candidate counts
    __shared__ float s_S, s_shift, s_mx, s_lo;
    __shared__ int   s_bt, s_cnt, s_bad, s_ovf;
    __shared__ float sh_p0, sh_tot;

    int* hist = (int*)arena;

    float* probs_out = tokens_first ? (out + B) : out;
    float* prow = probs_out + (size_t)row * V;
    const float* lrow = logits + (size_t)row * V;
    const float invT = 1.0f / temps[row];
    const int need = V < 1024 ? V : 1024;
    const int V4 = V >> 2;
    const float4* l4 = (const float4*)lrow;
    float4* p4 = (float4*)prow;
    const float4 z4 = make_float4(0.f, 0.f, 0.f, 0.f);

    // Aligned fast path: zero-stores are FOLDED into the phase-2 read loop so
    // reads and writes stream concurrently. Unaligned: scalar pre-zero (rare).
    const bool al = ((V & 3) == 0) && (((B & 3) == 0) || !tokens_first);
    if (!al) {
        for (int i = tid; i < V; i += NT) __stcs(prow + i, 0.f);
    }
    if (tid == 0) { s_cnt = 0; s_bad = 0; s_ovf = 0; s_bt = 1024; }

    // ---- Phase 1: contiguous-chunk 16k subsample histogram -> threshold ----
    if (V > CAP) {
        for (int t = tid; t < NBINS; t += NT) hist[t] = 0;
        __syncthreads();
        int Vq = V4 >> 2; if (Vq < 1) Vq = 1;
        for (int k = tid; k < 4096; k += NT) {
            int c = k >> 10;
            int t = k & 1023;
            int pos = c * Vq + (t % Vq);
            if (pos >= V4) pos = V4 - 1;
            float4 v = l4[pos];
            if (v.x > 2.0f) atomicAdd(&hist[bin_of(v.x)], 1);
            if (v.y > 2.0f) atomicAdd(&hist[bin_of(v.y)], 1);
            if (v.z > 2.0f) atomicAdd(&hist[bin_of(v.z)], 1);
            if (v.w > 2.0f) atomicAdd(&hist[bin_of(v.w)], 1);
        }
        __syncthreads();
        const int subN = 16384;
        int tgt = (int)(((long long)need * 31LL * subN) / (20LL * (long long)V));
        if (tgt < 1) tgt = 1;
        int b = 2047 - tid;
        int v = (tid < 960) ? hist[b] : 0;
        int sfx = block_incl_scan_int(v, iwsum, lane, wid);
        if (tid < 960 && sfx >= tgt && sfx - v < tgt) s_bt = b;
        __syncthreads();
    }
    const float xthr = (V > CAP) ? ((float)s_bt * 0.03125f - 32.0f) : -FLT_MAX;
    if (tid == 0) s_lo = xthr;
    __syncthreads();

    // ---- Phase 2: fused sweep: zero-store + load + max + sum(__expf) + gather ----
    const int wbase = row * CAP + wid * WSEG;
    int wcnt = 0;

    #define GATHER4(vv, bi)                                                              \
        { _Pragma("unroll")                                                              \
          for (int c = 0; c < 4; c++) {                                                  \
            float x = (c == 0) ? (vv).x : (c == 1) ? (vv).y : (c == 2) ? (vv).z : (vv).w;\
            bool pred = (x >= xthr);                                                     \
            unsigned m = __ballot_sync(0xffffffffu, pred);                               \
            int pos = wcnt + __popc(m & lmlt);                                           \
            if (pred && pos < WSEG) { g_cval[wbase + pos] = x;                           \
                                      g_cidx[wbase + pos] = ((bi) << 2) + c; }           \
            wcnt += __popc(m); }                                                         \
        }

    float sA = 0.f, sB = 0.f, sC = 0.f, sD = 0.f, mx = -FLT_MAX;
    int i = tid;
    for (; i + 3 * NT < V4; i += 4 * NT) {
        float4 va = l4[i];
        float4 vb = l4[i + NT];
        float4 vc = l4[i + 2 * NT];
        float4 vd = l4[i + 3 * NT];
        if (al) {
            __stcs(p4 + i, z4);
            __stcs(p4 + i + NT, z4);
            __stcs(p4 + i + 2 * NT, z4);
            __stcs(p4 + i + 3 * NT, z4);
        }
        mx = fmaxf(mx, fmaxf(fmaxf(va.x, va.y), fmaxf(va.z, va.w)));
        mx = fmaxf(mx, fmaxf(fmaxf(vb.x, vb.y), fmaxf(vb.z, vb.w)));
        mx = fmaxf(mx, fmaxf(fmaxf(vc.x, vc.y), fmaxf(vc.z, vc.w)));
        mx = fmaxf(mx, fmaxf(fmaxf(vd.x, vd.y), fmaxf(vd.z, vd.w)));
        sA += __expf(va.x * invT) + __expf(va.y * invT) + __expf(va.z * invT) + __expf(va.w * invT);
        sB += __expf(vb.x * invT) + __expf(vb.y * invT) + __expf(vb.z * invT) + __expf(vb.w * invT);
        sC += __expf(vc.x * invT) + __expf(vc.y * invT) + __expf(vc.z * invT) + __expf(vc.w * invT);
        sD += __expf(vd.x * invT) + __expf(vd.y * invT) + __expf(vd.z * invT) + __expf(vd.w * invT);
        GATHER4(va, i);
        GATHER4(vb, i + NT);
        GATHER4(vc, i + 2 * NT);
        GATHER4(vd, i + 3 * NT);
    }
    for (; i < V4; i += NT) {        // whole warps iterate together (ballot-safe)
        float4 v = l4[i];
        if (al) __stcs(p4 + i, z4);
        mx = fmaxf(mx, fmaxf(fmaxf(v.x, v.y), fmaxf(v.z, v.w)));
        sA += __expf(v.x * invT) + __expf(v.y * invT) + __expf(v.z * invT) + __expf(v.w * invT);
        GATHER4(v, i);
    }
    #undef GATHER4
    float s = (sA + sB) + (sC + sD);
    // tail (V % 4): whole-warp iteration with bounds predication (ballot-safe)
    for (int t = (V4 << 2) + tid; t - lane < V; t += NT) {
        bool in = t < V;
        float x = in ? lrow[t] : -FLT_MAX;
        if (in) {
            if (al) __stcs(prow + t, 0.f);
            mx = fmaxf(mx, x);
            s += __expf(x * invT);
        }
        bool pred = in && (x >= xthr);
        unsigned m = __ballot_sync(0xffffffffu, pred);
        int pos = wcnt + __popc(m & lmlt);
        if (pred && pos < WSEG) { g_cval[wbase + pos] = x; g_cidx[wbase + pos] = t; }
        wcnt += __popc(m);
    }
    if (lane == 0) scnt[wid] = wcnt;
    if (wcnt > WSEG && lane == 0) atomicExch(&s_ovf, 1);

    // ---- Phase 3: reductions + overflow guard + verify ----
    s = warp_red_sum(s);
    if (lane == 0) wred[wid] = s;
    __syncthreads();
    if (wid == 0) { float t = warp_red_sum(wred[lane]); if (lane == 0) s_S = t; }
    __syncthreads();
    mx = warp_red_max(mx);
    if (lane == 0) wred[wid] = mx;
    __syncthreads();
    if (wid == 0) {
        float t = warp_red_max(wred[lane]);
        if (lane == 0) {
            s_mx = t;
            float mxT = t * invT;
            s_shift = (mxT > 80.f || !isfinite(s_S)) ? mxT : 0.f;
        }
    }
    __syncthreads();
    const float shift = s_shift;
    if (shift != 0.f) {        // rare overflow-safe recompute (precise path)
        s = 0.f;
        for (int t = tid; t < V; t += NT) s += expf(lrow[t] * invT - shift);
        s = warp_red_sum(s);
        if (lane == 0) wred[wid] = s;
        __syncthreads();
        if (wid == 0) { float t = warp_red_sum(wred[lane]); if (lane == 0) s_S = t; }
        __syncthreads();
    }

    // total candidate count
    if (wid == 0) {
        int c = scnt[lane];
        #pragma unroll
        for (int o = 16; o; o >>= 1) c += __shfl_xor_sync(0xffffffffu, c, o);
        if (lane == 0) s_cnt = c;
    }
    __syncthreads();
    int C = s_cnt;
    bool segmented = (V > CAP);
    bool bad = segmented && (s_ovf || !(C >= need && C <= 2048));

    if ((V > CAP && bad) || V <= CAP) {
        // FALLBACK path: exact coarse histogram -> contiguous re-gather (rare),
        // or small-V direct copy. Produces contiguous g_cval[row*CAP + 0..C).
        segmented = false;
        if (V <= CAP) {
            for (int t = tid; t < V; t += NT) { g_cval[row * CAP + t] = lrow[t]; g_cidx[row * CAP + t] = t; }
            if (tid == 0) s_cnt = V;
            __syncthreads();
        } else {
            for (int t = tid; t < NBINS; t += NT) hist[t] = 0;
            __syncthreads();
            for (int t = tid; t < V; t += NT) atomicAdd(&hist[bin_of(lrow[t])], 1);
            __syncthreads();
            if (tid == 0) {
                int acc = 0, bt2 = 0;
                for (int b = NBINS - 1; b >= 0; b--) {
                    int na = acc + hist[b];
                    if (na >= need) { bt2 = (na <= CAP) ? b : (b + 1); break; }
                    acc = na;
                }
                s_bt = bt2; s_cnt = 0;
                s_lo = (float)bt2 * 0.03125f - 32.0f - 0.0625f;
            }
            __syncthreads();
            const int bt2 = s_bt;
            for (int t = tid; t < V; t += NT) {
                float x = lrow[t];
                if (bin_of(x) >= bt2) {
                    int pos = atomicAdd(&s_cnt, 1);
                    if (pos < CAP) { g_cval[row * CAP + pos] = x; g_cidx[row * CAP + pos] = t; }
                }
            }
            __syncthreads();
        }
        C = s_cnt;
    }
    C = C < CAP ? C : CAP;
    __syncthreads();

    // ---- Phase 4: histogram ranking over 4 segmented slots per thread ----
    const float lo = s_lo, hi = s_mx;
    const float range = hi - lo;
    int*      bins = (int*)arena;
    unsigned* skv  = arena + 4096;
    unsigned* skp  = arena + 6144;
    unsigned *pk = skv, *pp = skp;

    bool fast = segmented && (C <= 2048) && (range > 0.f) && isfinite(range);

    if (fast) {
        const float scale = (float)FB / range;
        float    xv[4];
        int      xi[4], xb[4];
        bool     val[4];
        #pragma unroll
        for (int e = 0; e < 4; e++) {
            int slot = tid + e * NT;                // 0..4095
            int w = slot >> 7, j = slot & (WSEG - 1);
            val[e] = j < scnt[w];
            if (val[e]) { xv[e] = g_cval[row * CAP + slot]; xi[e] = g_cidx[row * CAP + slot]; }
        }
        #pragma unroll
        for (int t = 0; t < 4; t++) bins[tid + t * NT] = 0;
        __syncthreads();
        #pragma unroll
        for (int e = 0; e < 4; e++) {
            if (val[e]) {
                int b = (int)((xv[e] - lo) * scale); b = b < 0 ? 0 : (b > FB - 1 ? FB - 1 : b);
                xb[e] = b;
                atomicAdd(&bins[b], 1);
            }
        }
        __syncthreads();
        int c0c = bins[4095 - 4 * tid];
        int c1c = bins[4094 - 4 * tid];
        int c2c = bins[4093 - 4 * tid];
        int c3c = bins[4092 - 4 * tid];
        int tot4 = c0c + c1c + c2c + c3c;
        int base = block_incl_scan_int(tot4, iwsum, lane, wid) - tot4;
        bins[4095 - 4 * tid] = base;
        bins[4094 - 4 * tid] = base + c0c;
        bins[4093 - 4 * tid] = base + c0c + c1c;
        bins[4092 - 4 * tid] = base + c0c + c1c + c2c;
        __syncthreads();
        #pragma unroll
        for (int e = 0; e < 4; e++) {
            if (val[e]) {
                int sl = atomicAdd(&bins[xb[e]], 1);
                skv[sl] = fmap(xv[e]); skp[sl] = (unsigned)xi[e];
            }
        }
        __syncthreads();
        // fixup within-bin order: insertion sort on contiguous same-bin runs
        #pragma unroll
        for (int e = 0; e < 2; e++) {
            int ii = tid + e * 1024;
            if (ii < C) {
                int bi = (int)((funmap(skv[ii]) - lo) * scale); bi = bi < 0 ? 0 : (bi > FB - 1 ? FB - 1 : bi);
                int bp = -1;
                if (ii > 0) {
                    bp = (int)((funmap(skv[ii - 1]) - lo) * scale); bp = bp < 0 ? 0 : (bp > FB - 1 ? FB - 1 : bp);
                }
                if (bi != bp) {                       // run start
                    int L = 1;
                    while (ii + L < C && L <= 16) {
                        int bn = (int)((funmap(skv[ii + L]) - lo) * scale); bn = bn < 0 ? 0 : (bn > FB - 1 ? FB - 1 : bn);
                        if (bn != bi) break;
                        L++;
                    }
                    if (L > 16) { atomicExch(&s_bad, 1); }
                    else if (L > 1) {
                        unsigned lk[16], lp[16];
                        for (int t = 0; t < L; t++) { lk[t] = skv[ii + t]; lp[t] = skp[ii + t]; }
                        for (int a = 1; a < L; a++) {
                            unsigned ck = lk[a], cp = lp[a];
                            int b2 = a - 1;
                            while (b2 >= 0 && !kv_gt(lk[b2], lp[b2], ck, cp)) {
                                lk[b2 + 1] = lk[b2]; lp[b2 + 1] = lp[b2]; b2--;
                            }
                            lk[b2 + 1] = ck; lp[b2 + 1] = cp;
                        }
                        for (int t = 0; t < L; t++) { skv[ii + t] = lk[t]; skp[ii + t] = lp[t]; }
                    }
                }
            }
        }
        __syncthreads();
        if (s_bad) fast = false;
        __syncthreads();
    }

    if (!fast) {
        // exact bitonic on 4096 (rare). Needs contiguous candidates: compact first
        // if still segmented.
        if (segmented) {
            unsigned* ckv = arena;          // 4096
            unsigned* ckp = arena + 4096;   // 4096
            if (wid == 0) {
                int c = (lane < 32) ? scnt[lane] : 0;
                int inc = c;
                #pragma unroll
                for (int off = 1; off < 32; off <<= 1) {
                    int n = __shfl_up_sync(0xffffffffu, inc, off);
                    if (lane >= off) inc += n;
                }
                iwsum[lane] = inc - c;      // exclusive base per warp
            }
            __syncthreads();
            #pragma unroll
            for (int e = 0; e < 4; e++) {
                int slot = tid + e * NT;
                int w = slot >> 7, j = slot & (WSEG - 1);
                if (j < scnt[w]) {
                    int dst = iwsum[w] + j;
                    ckv[dst] = fmap(g_cval[row * CAP + slot]);
                    ckp[dst] = (unsigned)g_cidx[row * CAP + slot];
                }
            }
            __syncthreads();
            for (int ii = tid; ii < CAP; ii += NT) {
                if (ii >= C) { ckv[ii] = 0u; ckp[ii] = 0xFFFFFFFFu; }
            }
            __syncthreads();
        } else {
            unsigned* ckv = arena;
            unsigned* ckp = arena + 4096;
            for (int ii = tid; ii < CAP; ii += NT) {
                unsigned key = 0u, pay = 0xFFFFFFFFu;
                if (ii < C) { key = fmap(g_cval[row * CAP + ii]); pay = (unsigned)g_cidx[row * CAP + ii]; }
                ckv[ii] = key; ckp[ii] = pay;
            }
            __syncthreads();
        }
        unsigned* fkv = arena;
        unsigned* fkp = arena + 4096;
        for (int K = 2; K <= CAP; K <<= 1) {
            int j = K >> 1;
            for (; j >= 64; j >>= 1) {
                for (int c = tid; c < (CAP >> 1); c += NT) {
                    int ii = ((c & ~(j - 1)) << 1) | (c & (j - 1));
                    ce_sh(fkv, fkp, ii, j, K);
                }
                __syncthreads();
            }
            for (; j >= 1; j >>= 1) {
                for (int c = tid; c < (CAP >> 1); c += NT) {
                    int ii = ((c & ~(j - 1)) << 1) | (c & (j - 1));
                    ce_sh(fkv, fkp, ii, j, K);
                }
                __syncwarp();
            }
            __syncthreads();
        }
        pk = fkv; pp = fkp;
    }

    // ---- Phase 5: masks (reference order) + inverse-CDF sample + scatter ----
    const float S = s_S;
    float p = 0.f;
    int   myidx = 0;
    if (tid < C) {
        p = expf(funmap(pk[tid]) * invT - shift) / S;
        myidx = (int)pp[tid];
    }
    if (tid == 0) sh_p0 = p;

    float cumincl = block_incl_scan(p, wred, lane, wid);   // pre-mask cumsum

    const int   tk  = top_ks[row];
    const float tp  = top_ps[row];
    const float thr = sh_p0 * min_ps[row];
    float q = p;
    if (tid >= tk)        q = 0.f;   // top-k
    if (cumincl - q > tp) q = 0.f;   // top-p (cumsum computed pre-mask)
    if (q < thr)          q = 0.f;   // min-p

    float cq = block_incl_scan(q, wred, lane, wid);        // post-mask CDF numerator
    if (tid == NT - 1) sh_tot = cq;
    __syncthreads();
    const float tot  = sh_tot;
    const float uval = u[row];

    int rank = __syncthreads_count((cq / tot < uval) ? 1 : 0);
    if (rank > NT - 1) rank = NT - 1;
    if (rank > V - 1) rank = V - 1;

    if (tid == 0 && tokens_first) {
        out[row] = (float)(int)pp[rank];
    }
    if (q > 0.f) {
        prow[myidx] = q / tot;   // ordered after the fused zero stores by barriers
    }
}

extern "C" void kernel_launch(void* const* d_in, const int* in_sizes, int n_in,
                              void* d_out, int out_size)
{
    const float* logits = (const float*)d_in[0];
    const float* temps  = (const float*)d_in[1];
    const int*   topks  = (const int*)  d_in[2];
    const float* topps  = (const float*)d_in[3];
    const float* minps  = (const float*)d_in[4];
    const float* u      = (const float*)d_in[5];

    const int B = in_sizes[1];
    const int V = in_sizes[0] / B;
    float* out = (float*)d_out;
    int tokens_first = (out_size == B + B * V) ? 1 : 0;

    k_fused<<<B, NT>>>(logits, temps, topks, topps, minps, u, out, V, B, tokens_first);
}

// round 14
// speedup vs baseline: 2.1774x; 1.0120x over previous
#include <cuda_runtime.h>
#include <math.h>
#include <stdint.h>
#include <float.h>

#define MAXB  128
#define CAP   4096
#define NBINS 2048     // coarse subsample bins
#define FB    4096     // fine ranking bins
#define NT    1024
#define WSEG  128      // per-warp candidate segment (32 warps * 128 = CAP)

// Global candidate staging (written phase 2/3, read phase 4)
__device__ float g_cval[MAXB * CAP];
__device__ int   g_cidx[MAXB * CAP];

__device__ __forceinline__ int bin_of(float x) {
    int b = (int)floorf((x + 32.0f) * 32.0f);   // width 1/32 over [-32, 32]
    b = b < 0 ? 0 : b;
    return b > (NBINS - 1) ? (NBINS - 1) : b;
}

__device__ __forceinline__ float warp_red_sum(float v) {
    #pragma unroll
    for (int o = 16; o; o >>= 1) v += __shfl_xor_sync(0xffffffffu, v, o);
    return v;
}
__device__ __forceinline__ float warp_red_max(float v) {
    #pragma unroll
    for (int o = 16; o; o >>= 1) v = fmaxf(v, __shfl_xor_sync(0xffffffffu, v, o));
    return v;
}

__device__ __forceinline__ float block_incl_scan(float v, float* wsum, int lane, int wid) {
    #pragma unroll
    for (int off = 1; off < 32; off <<= 1) {
        float n = __shfl_up_sync(0xffffffffu, v, off);
        if (lane >= off) v += n;
    }
    __syncthreads();
    if (lane == 31) wsum[wid] = v;
    __syncthreads();
    if (wid == 0) {
        float w = wsum[lane];
        #pragma unroll
        for (int off = 1; off < 32; off <<= 1) {
            float n = __shfl_up_sync(0xffffffffu, w, off);
            if (lane >= off) w += n;
        }
        wsum[lane] = w;
    }
    __syncthreads();
    return v + (wid ? wsum[wid - 1] : 0.f);
}

__device__ __forceinline__ int block_incl_scan_int(int v, int* wsum, int lane, int wid) {
    #pragma unroll
    for (int off = 1; off < 32; off <<= 1) {
        int n = __shfl_up_sync(0xffffffffu, v, off);
        if (lane >= off) v += n;
    }
    __syncthreads();
    if (lane == 31) wsum[wid] = v;
    __syncthreads();
    if (wid == 0) {
        int w = wsum[lane];
        #pragma unroll
        for (int off = 1; off < 32; off <<= 1) {
            int n = __shfl_up_sync(0xffffffffu, w, off);
            if (lane >= off) w += n;
        }
        wsum[lane] = w;
    }
    __syncthreads();
    return v + (wid ? wsum[wid - 1] : 0);
}

// order-preserving float <-> u32
__device__ __forceinline__ unsigned fmap(float x) {
    unsigned fb = __float_as_uint(x);
    return (fb & 0x80000000u) ? ~fb : (fb | 0x80000000u);
}
__device__ __forceinline__ float funmap(unsigned mu) {
    unsigned fb = (mu & 0x80000000u) ? (mu & 0x7FFFFFFFu) : ~mu;
    return __uint_as_float(fb);
}

// descending order: larger key first, then smaller idx first
__device__ __forceinline__ bool kv_gt(unsigned k1, unsigned p1, unsigned k2, unsigned p2) {
    return (k1 > k2) || (k1 == k2 && p1 < p2);
}
__device__ __forceinline__ void ce_sh(unsigned* kv, unsigned* pv, int i, int j, int K) {
    unsigned k1 = kv[i], p1 = pv[i], k2 = kv[i + j], p2 = pv[i + j];
    bool sw = ((i & K) == 0) ? kv_gt(k2, p2, k1, p1) : kv_gt(k1, p1, k2, p2);
    if (sw) { kv[i] = k2; pv[i] = p2; kv[i + j] = k1; pv[i + j] = p1; }
}

// ============================ ONE fused kernel ============================
__global__ void __launch_bounds__(NT) k_fused(const float* __restrict__ logits,
                                              const float* __restrict__ temps,
                                              const int*   __restrict__ top_ks,
                                              const float* __restrict__ top_ps,
                                              const float* __restrict__ min_ps,
                                              const float* __restrict__ u,
                                              float* __restrict__ out,
                                              int V, int B, int tokens_first)
{
    const int row = blockIdx.x;
    const int tid = threadIdx.x;
    const int lane = tid & 31, wid = tid >> 5;
    const unsigned lmlt = (1u << lane) - 1u;

    __shared__ unsigned arena[8192];       // 32 KB phase-aliased
    __shared__ float wred[32];
    __shared__ int   iwsum[32];
    __shared__ int   scnt[32];             // per-warp candidate counts
    __shared__ float s_S, s_shift, s_mx, s_lo;
    __shared__ int   s_bt, s_cnt, s_bad, s_ovf;
    __shared__ float sh_p0, sh_tot;

    int* hist = (int*)arena;

    float* probs_out = tokens_first ? (out + B) : out;
    float* prow = probs_out + (size_t)row * V;
    const float* lrow = logits + (size_t)row * V;
    const float invT = 1.0f / temps[row];
    const int need = V < 1024 ? V : 1024;
    const int V4 = V >> 2;
    const float4* l4 = (const float4*)lrow;
    float4* p4 = (float4*)prow;
    const float4 z4 = make_float4(0.f, 0.f, 0.f, 0.f);

    // Aligned fast path: zero-stores folded into the sweep. Unaligned: pre-zero.
    const bool al = ((V & 3) == 0) && (((B & 3) == 0) || !tokens_first);
    if (!al) {
        for (int i = tid; i < V; i += NT) __stcs(prow + i, 0.f);
    }
    if (tid == 0) { s_cnt = 0; s_bad = 0; s_ovf = 0; s_bt = 1024; }

    // ---- Phase 1: contiguous-chunk 16k subsample histogram -> threshold ----
    if (V > CAP) {
        for (int t = tid; t < NBINS; t += NT) hist[t] = 0;
        __syncthreads();
        int Vq = V4 >> 2; if (Vq < 1) Vq = 1;
        for (int k = tid; k < 4096; k += NT) {
            int c = k >> 10;
            int t = k & 1023;
            int pos = c * Vq + (t % Vq);
            if (pos >= V4) pos = V4 - 1;
            float4 v = l4[pos];
            if (v.x > 2.0f) atomicAdd(&hist[bin_of(v.x)], 1);
            if (v.y > 2.0f) atomicAdd(&hist[bin_of(v.y)], 1);
            if (v.z > 2.0f) atomicAdd(&hist[bin_of(v.z)], 1);
            if (v.w > 2.0f) atomicAdd(&hist[bin_of(v.w)], 1);
        }
        __syncthreads();
        const int subN = 16384;
        int tgt = (int)(((long long)need * 31LL * subN) / (20LL * (long long)V));
        if (tgt < 1) tgt = 1;
        int b = 2047 - tid;
        int v = (tid < 960) ? hist[b] : 0;
        int sfx = block_incl_scan_int(v, iwsum, lane, wid);
        if (tid < 960 && sfx >= tgt && sfx - v < tgt) s_bt = b;
        __syncthreads();
    }
    const float xthr = (V > CAP) ? ((float)s_bt * 0.03125f - 32.0f) : -FLT_MAX;
    if (tid == 0) s_lo = xthr;
    __syncthreads();

    // ---- Phase 2: minimal sweep: zero-store + load + sum(__expf) + gather ----
    // NO max here: the global max is always >= xthr, hence always a candidate
    // (when the gather didn't overflow); it is recovered from the candidate
    // segments in phase 3. Ballots per float4 are batched (independent issue).
    const int wbase = row * CAP + wid * WSEG;
    int wcnt = 0;

    #define GATHER4(vv, bi)                                                              \
        { bool p0 = (vv).x >= xthr, p1g = (vv).y >= xthr,                                \
               p2g = (vv).z >= xthr, p3g = (vv).w >= xthr;                               \
          unsigned m0 = __ballot_sync(0xffffffffu, p0);                                  \
          unsigned m1 = __ballot_sync(0xffffffffu, p1g);                                 \
          unsigned m2 = __ballot_sync(0xffffffffu, p2g);                                 \
          unsigned m3 = __ballot_sync(0xffffffffu, p3g);                                 \
          int c0 = __popc(m0), c1 = __popc(m1), c2 = __popc(m2), c3 = __popc(m3);        \
          int o0 = wcnt + __popc(m0 & lmlt);                                             \
          int o1 = wcnt + c0 + __popc(m1 & lmlt);                                        \
          int o2 = wcnt + c0 + c1 + __popc(m2 & lmlt);                                   \
          int o3 = wcnt + c0 + c1 + c2 + __popc(m3 & lmlt);                              \
          if (p0 && o0 < WSEG) { g_cval[wbase + o0] = (vv).x; g_cidx[wbase + o0] = ((bi) << 2) + 0; } \
          if (p1g && o1 < WSEG) { g_cval[wbase + o1] = (vv).y; g_cidx[wbase + o1] = ((bi) << 2) + 1; } \
          if (p2g && o2 < WSEG) { g_cval[wbase + o2] = (vv).z; g_cidx[wbase + o2] = ((bi) << 2) + 2; } \
          if (p3g && o3 < WSEG) { g_cval[wbase + o3] = (vv).w; g_cidx[wbase + o3] = ((bi) << 2) + 3; } \
          wcnt += (c0 + c1) + (c2 + c3); }

    float sA = 0.f, sB = 0.f, sC = 0.f, sD = 0.f;
    int i = tid;
    for (; i + 3 * NT < V4; i += 4 * NT) {
        if (al) {
            __stcs(p4 + i, z4);
            __stcs(p4 + i + NT, z4);
            __stcs(p4 + i + 2 * NT, z4);
            __stcs(p4 + i + 3 * NT, z4);
        }
        float4 va = l4[i];
        float4 vb = l4[i + NT];
        float4 vc = l4[i + 2 * NT];
        float4 vd = l4[i + 3 * NT];
        sA += __expf(va.x * invT) + __expf(va.y * invT) + __expf(va.z * invT) + __expf(va.w * invT);
        sB += __expf(vb.x * invT) + __expf(vb.y * invT) + __expf(vb.z * invT) + __expf(vb.w * invT);
        sC += __expf(vc.x * invT) + __expf(vc.y * invT) + __expf(vc.z * invT) + __expf(vc.w * invT);
        sD += __expf(vd.x * invT) + __expf(vd.y * invT) + __expf(vd.z * invT) + __expf(vd.w * invT);
        GATHER4(va, i);
        GATHER4(vb, i + NT);
        GATHER4(vc, i + 2 * NT);
        GATHER4(vd, i + 3 * NT);
    }
    for (; i < V4; i += NT) {        // whole warps iterate together (ballot-safe)
        if (al) __stcs(p4 + i, z4);
        float4 v = l4[i];
        sA += __expf(v.x * invT) + __expf(v.y * invT) + __expf(v.z * invT) + __expf(v.w * invT);
        GATHER4(v, i);
    }
    #undef GATHER4
    float s = (sA + sB) + (sC + sD);
    // tail (V % 4): whole-warp iteration with bounds predication (ballot-safe)
    for (int t = (V4 << 2) + tid; t - lane < V; t += NT) {
        bool in = t < V;
        float x = in ? lrow[t] : -FLT_MAX;
        if (in) {
            if (al) __stcs(prow + t, 0.f);
            s += __expf(x * invT);
        }
        bool pred = in && (x >= xthr);
        unsigned m = __ballot_sync(0xffffffffu, pred);
        int pos = wcnt + __popc(m & lmlt);
        if (pred && pos < WSEG) { g_cval[wbase + pos] = x; g_cidx[wbase + pos] = t; }
        wcnt += __popc(m);
    }
    if (lane == 0) scnt[wid] = wcnt;
    if (wcnt > WSEG && lane == 0) atomicExch(&s_ovf, 1);

    // ---- Phase 3: S-reduction, count, path selection, max, shift guard ----
    s = warp_red_sum(s);
    if (lane == 0) wred[wid] = s;
    __syncthreads();                               // also publishes scnt, s_ovf
    if (wid == 0) { float t = warp_red_sum(wred[lane]); if (lane == 0) s_S = t; }
    if (wid == 1) {                                // count reduce in parallel warp
        int c = scnt[lane];
        #pragma unroll
        for (int o = 16; o; o >>= 1) c += __shfl_xor_sync(0xffffffffu, c, o);
        if (lane == 0) s_cnt = c;
    }
    __syncthreads();

    int C = s_cnt;
    bool segmented = (V > CAP);
    const bool bad = segmented && (s_ovf || !(C >= need && C <= 2048));

    // candidate slots (loaded once; reused by phase 4 fast path)
    float xv[4]; int xi[4]; bool val[4];
    #pragma unroll
    for (int e = 0; e < 4; e++) val[e] = false;

    float mx = -FLT_MAX;
    if (segmented && !bad) {
        // max over candidate segments == global max (no overflow, thr <= max)
        #pragma unroll
        for (int e = 0; e < 4; e++) {
            int slot = tid + e * NT;                // 0..4095
            int w = slot >> 7, j = slot & (WSEG - 1);
            val[e] = j < scnt[w];
            if (val[e]) {
                xv[e] = g_cval[row * CAP + slot];
                xi[e] = g_cidx[row * CAP + slot];
                mx = fmaxf(mx, xv[e]);
            }
        }
    } else if (V <= CAP) {
        segmented = false;
        for (int t = tid; t < V; t += NT) { g_cval[row * CAP + t] = lrow[t]; g_cidx[row * CAP + t] = t; }
        if (tid == 0) s_cnt = V;
        __syncthreads();
        C = V;
        for (int t = tid; t < V; t += NT) mx = fmaxf(mx, lrow[t]);   // == row max
    } else {
        // FALLBACK (~never): exact coarse histogram + exact max in one pass
        segmented = false;
        for (int t = tid; t < NBINS; t += NT) hist[t] = 0;
        __syncthreads();
        for (int t = tid; t < V; t += NT) {
            float x = lrow[t];
            mx = fmaxf(mx, x);
            atomicAdd(&hist[bin_of(x)], 1);
        }
        __syncthreads();
        if (tid == 0) {
            int acc = 0, bt2 = 0;
            for (int b = NBINS - 1; b >= 0; b--) {
                int na = acc + hist[b];
                if (na >= need) { bt2 = (na <= CAP) ? b : (b + 1); break; }
                acc = na;
            }
            s_bt = bt2; s_cnt = 0;
            s_lo = (float)bt2 * 0.03125f - 32.0f - 0.0625f;
        }
        __syncthreads();
        const int bt2 = s_bt;
        for (int t = tid; t < V; t += NT) {
            float x = lrow[t];
            if (bin_of(x) >= bt2) {
                int pos = atomicAdd(&s_cnt, 1);
                if (pos < CAP) { g_cval[row * CAP + pos] = x; g_cidx[row * CAP + pos] = t; }
            }
        }
        __syncthreads();
        C = s_cnt;
    }
    C = C < CAP ? C : CAP;

    // block-reduce max
    mx = warp_red_max(mx);
    __syncthreads();
    if (lane == 0) wred[wid] = mx;
    __syncthreads();
    if (wid == 0) {
        float t = warp_red_max(wred[lane]);
        if (lane == 0) {
            s_mx = t;
            float mxT = t * invT;
            s_shift = (mxT > 80.f || !isfinite(s_S)) ? mxT : 0.f;
        }
    }
    __syncthreads();
    const float shift = s_shift;
    if (shift != 0.f) {        // rare overflow-safe recompute (precise path)
        float s2 = 0.f;
        for (int t = tid; t < V; t += NT) s2 += expf(lrow[t] * invT - shift);
        s2 = warp_red_sum(s2);
        if (lane == 0) wred[wid] = s2;
        __syncthreads();
        if (wid == 0) { float t = warp_red_sum(wred[lane]); if (lane == 0) s_S = t; }
        __syncthreads();
    }

    // ---- Phase 4: histogram ranking ----
    const float lo = s_lo, hi = s_mx;
    const float range = hi - lo;
    int*      bins = (int*)arena;
    unsigned* skv  = arena + 4096;
    unsigned* skp  = arena + 6144;
    unsigned *pk = skv, *pp = skp;

    bool fast = segmented && (C <= 2048) && (range > 0.f) && isfinite(range);

    if (fast) {
        const float scale = (float)FB / range;
        int xb[4];
        #pragma unroll
        for (int t = 0; t < 4; t++) bins[tid + t * NT] = 0;
        __syncthreads();
        #pragma unroll
        for (int e = 0; e < 4; e++) {
            if (val[e]) {
                int b = (int)((xv[e] - lo) * scale); b = b < 0 ? 0 : (b > FB - 1 ? FB - 1 : b);
                xb[e] = b;
                atomicAdd(&bins[b], 1);
            }
        }
        __syncthreads();
        int c0c = bins[4095 - 4 * tid];
        int c1c = bins[4094 - 4 * tid];
        int c2c = bins[4093 - 4 * tid];
        int c3c = bins[4092 - 4 * tid];
        int tot4 = c0c + c1c + c2c + c3c;
        int base = block_incl_scan_int(tot4, iwsum, lane, wid) - tot4;
        bins[4095 - 4 * tid] = base;
        bins[4094 - 4 * tid] = base + c0c;
        bins[4093 - 4 * tid] = base + c0c + c1c;
        bins[4092 - 4 * tid] = base + c0c + c1c + c2c;
        __syncthreads();
        #pragma unroll
        for (int e = 0; e < 4; e++) {
            if (val[e]) {
                int sl = atomicAdd(&bins[xb[e]], 1);
                skv[sl] = fmap(xv[e]); skp[sl] = (unsigned)xi[e];
            }
        }
        __syncthreads();
        // fixup within-bin order: insertion sort on contiguous same-bin runs
        #pragma unroll
        for (int e = 0; e < 2; e++) {
            int ii = tid + e * 1024;
            if (ii < C) {
                int bi = (int)((funmap(skv[ii]) - lo) * scale); bi = bi < 0 ? 0 : (bi > FB - 1 ? FB - 1 : bi);
                int bp = -1;
                if (ii > 0) {
                    bp = (int)((funmap(skv[ii - 1]) - lo) * scale); bp = bp < 0 ? 0 : (bp > FB - 1 ? FB - 1 : bp);
                }
                if (bi != bp) {                       // run start
                    int L = 1;
                    while (ii + L < C && L <= 16) {
                        int bn = (int)((funmap(skv[ii + L]) - lo) * scale); bn = bn < 0 ? 0 : (bn > FB - 1 ? FB - 1 : bn);
                        if (bn != bi) break;
                        L++;
                    }
                    if (L > 16) { atomicExch(&s_bad, 1); }
                    else if (L > 1) {
                        unsigned lk[16], lp[16];
                        for (int t = 0; t < L; t++) { lk[t] = skv[ii + t]; lp[t] = skp[ii + t]; }
                        for (int a = 1; a < L; a++) {
                            unsigned ck = lk[a], cp = lp[a];
                            int b2 = a - 1;
                            while (b2 >= 0 && !kv_gt(lk[b2], lp[b2], ck, cp)) {
                                lk[b2 + 1] = lk[b2]; lp[b2 + 1] = lp[b2]; b2--;
                            }
                            lk[b2 + 1] = ck; lp[b2 + 1] = cp;
                        }
                        for (int t = 0; t < L; t++) { skv[ii + t] = lk[t]; skp[ii + t] = lp[t]; }
                    }
                }
            }
        }
        __syncthreads();
        if (s_bad) fast = false;
        __syncthreads();
    }

    if (!fast) {
        // exact bitonic on 4096 (rare). Compact segmented candidates first.
        if (segmented) {
            unsigned* ckv = arena;          // 4096
            unsigned* ckp = arena + 4096;   // 4096
            if (wid == 0) {
                int c = (lane < 32) ? scnt[lane] : 0;
                int inc = c;
                #pragma unroll
                for (int off = 1; off < 32; off <<= 1) {
                    int n = __shfl_up_sync(0xffffffffu, inc, off);
                    if (lane >= off) inc += n;
                }
                iwsum[lane] = inc - c;      // exclusive base per warp
            }
            __syncthreads();
            #pragma unroll
            for (int e = 0; e < 4; e++) {
                int slot = tid + e * NT;
                int w = slot >> 7, j = slot & (WSEG - 1);
                if (j < scnt[w]) {
                    int dst = iwsum[w] + j;
                    ckv[dst] = fmap(g_cval[row * CAP + slot]);
                    ckp[dst] = (unsigned)g_cidx[row * CAP + slot];
                }
            }
            __syncthreads();
            for (int ii = tid; ii < CAP; ii += NT) {
                if (ii >= C) { ckv[ii] = 0u; ckp[ii] = 0xFFFFFFFFu; }
            }
            __syncthreads();
        } else {
            unsigned* ckv = arena;
            unsigned* ckp = arena + 4096;
            for (int ii = tid; ii < CAP; ii += NT) {
                unsigned key = 0u, pay = 0xFFFFFFFFu;
                if (ii < C) { key = fmap(g_cval[row * CAP + ii]); pay = (unsigned)g_cidx[row * CAP + ii]; }
                ckv[ii] = key; ckp[ii] = pay;
            }
            __syncthreads();
        }
        unsigned* fkv = arena;
        unsigned* fkp = arena + 4096;
        for (int K = 2; K <= CAP; K <<= 1) {
            int j = K >> 1;
            for (; j >= 64; j >>= 1) {
                for (int c = tid; c < (CAP >> 1); c += NT) {
                    int ii = ((c & ~(j - 1)) << 1) | (c & (j - 1));
                    ce_sh(fkv, fkp, ii, j, K);
                }
                __syncthreads();
            }
            for (; j >= 1; j >>= 1) {
                for (int c = tid; c < (CAP >> 1); c += NT) {
                    int ii = ((c & ~(j - 1)) << 1) | (c & (j - 1));
                    ce_sh(fkv, fkp, ii, j, K);
                }
                __syncwarp();
            }
            __syncthreads();
        }
        pk = fkv; pp = fkp;
    }

    // ---- Phase 5: masks (reference order) + inverse-CDF sample + scatter ----
    const float S = s_S;
    float p = 0.f;
    int   myidx = 0;
    if (tid < C) {
        p = expf(funmap(pk[tid]) * invT - shift) / S;
        myidx = (int)pp[tid];
    }
    if (tid == 0) sh_p0 = p;

    float cumincl = block_incl_scan(p, wred, lane, wid);   // pre-mask cumsum

    const int   tk  = top_ks[row];
    const float tp  = top_ps[row];
    const float thr = sh_p0 * min_ps[row];
    float q = p;
    if (tid >= tk)        q = 0.f;   // top-k
    if (cumincl - q > tp) q = 0.f;   // top-p (cumsum computed pre-mask)
    if (q < thr)          q = 0.f;   // min-p

    float cq = block_incl_scan(q, wred, lane, wid);        // post-mask CDF numerator
    if (tid == NT - 1) sh_tot = cq;
    __syncthreads();
    const float tot  = sh_tot;
    const float uval = u[row];

    int rank = __syncthreads_count((cq / tot < uval) ? 1 : 0);
    if (rank > NT - 1) rank = NT - 1;
    if (rank > V - 1) rank = V - 1;

    if (tid == 0 && tokens_first) {
        out[row] = (float)(int)pp[rank];
    }
    if (q > 0.f) {
        prow[myidx] = q / tot;   // ordered after the fused zero stores by barriers
    }
}

extern "C" void kernel_launch(void* const* d_in, const int* in_sizes, int n_in,
                              void* d_out, int out_size)
{
    const float* logits = (const float*)d_in[0];
    const float* temps  = (const float*)d_in[1];
    const int*   topks  = (const int*)  d_in[2];
    const float* topps  = (const float*)d_in[3];
    const float* minps  = (const float*)d_in[4];
    const float* u      = (const float*)d_in[5];

    const int B = in_sizes[1];
    const int V = in_sizes[0] / B;
    float* out = (float*)d_out;
    int tokens_first = (out_size == B + B * V) ? 1 : 0;

    k_fused<<<B, NT>>>(logits, temps, topks, topps, minps, u, out, V, B, tokens_first);
}